// round 12
// baseline (speedup 1.0000x reference)
#include <cuda_runtime.h>
#include <cuda_bf16.h>
#include <stdint.h>
#include <math.h>

#define B_ 2
#define S_ 2048
#define D_ 1024
#define H_ 16
#define HD_ 64
#define BS_ (B_*S_)
#define NROWS_ (B_*H_*S_)
#define NTILE_ (S_/128)

// ---------------- bf16 split scratch ----------------
__device__ __nv_bfloat16 g_iQh[BS_*D_], g_iQl[BS_*D_];
__device__ __nv_bfloat16 g_iKh[BS_*D_], g_iKl[BS_*D_];
__device__ __nv_bfloat16 g_iVh[BS_*D_], g_iVl[BS_*D_];
__device__ __nv_bfloat16 g_wqh[D_*D_], g_wql[D_*D_];
__device__ __nv_bfloat16 g_wkh[D_*D_], g_wkl[D_*D_];
__device__ __nv_bfloat16 g_wvh[D_*D_], g_wvl[D_*D_];
__device__ __nv_bfloat16 g_woh[D_*D_], g_wol[D_*D_];
__device__ __nv_bfloat16 g_qh[BS_*D_], g_ql[BS_*D_];
__device__ __nv_bfloat16 g_kh[BS_*D_], g_kl[BS_*D_];
__device__ __nv_bfloat16 g_vth[BS_*D_], g_vtl[BS_*D_];   // [B,H,HD,S]
__device__ __nv_bfloat16 g_cath[BS_*D_], g_catl[BS_*D_]; // [B,S,D]
__device__ float g_psum[NROWS_*NTILE_];
__device__ float g_inv[NROWS_];

// ---------------- helpers ----------------
__device__ __forceinline__ uint32_t smem_u32(const void* p){
    uint32_t a;
    asm("{ .reg .u64 t; cvta.to.shared.u64 t, %1; cvt.u32.u64 %0, t; }" : "=r"(a) : "l"(p));
    return a;
}
__device__ __forceinline__ void cp_async16(uint32_t saddr, const void* g){
    asm volatile("cp.async.cg.shared.global [%0], [%1], 16;" :: "r"(saddr), "l"(g));
}
#define CP_COMMIT() asm volatile("cp.async.commit_group;" ::: "memory")
#define CP_WAIT1()  asm volatile("cp.async.wait_group 1;"  ::: "memory")

__device__ __forceinline__ void ldmat_x4(uint32_t& r0, uint32_t& r1, uint32_t& r2,
                                         uint32_t& r3, uint32_t addr){
    asm volatile("ldmatrix.sync.aligned.m8n8.x4.shared.b16 {%0,%1,%2,%3}, [%4];"
        : "=r"(r0), "=r"(r1), "=r"(r2), "=r"(r3) : "r"(addr));
}
__device__ __forceinline__ void mma_bf16(float& d0, float& d1, float& d2, float& d3,
                                         uint32_t a0, uint32_t a1, uint32_t a2, uint32_t a3,
                                         uint32_t b0, uint32_t b1){
    asm volatile("mma.sync.aligned.m16n8k16.row.col.f32.bf16.bf16.f32 "
        "{%0,%1,%2,%3}, {%4,%5,%6,%7}, {%8,%9}, {%0,%1,%2,%3};"
        : "+f"(d0), "+f"(d1), "+f"(d2), "+f"(d3)
        : "r"(a0), "r"(a1), "r"(a2), "r"(a3), "r"(b0), "r"(b1));
}
__device__ __forceinline__ uint32_t pack_bf16x2(float a, float b){
    __nv_bfloat162 v = __floats2bfloat162_rn(a, b);
    return *reinterpret_cast<uint32_t*>(&v);
}
__device__ __forceinline__ void split2(float a, float b, uint32_t& h, uint32_t& l){
    __nv_bfloat16 ha = __float2bfloat16(a), hb = __float2bfloat16(b);
    h = ((uint32_t)__bfloat16_as_ushort(ha)) | (((uint32_t)__bfloat16_as_ushort(hb)) << 16);
    l = pack_bf16x2(a - __bfloat162float(ha), b - __bfloat162float(hb));
}
__device__ __forceinline__ void split8(const float4& x0, const float4& x1,
                                       uint4& h, uint4& l){
    split2(x0.x, x0.y, h.x, l.x);
    split2(x0.z, x0.w, h.y, l.y);
    split2(x1.x, x1.y, h.z, l.z);
    split2(x1.z, x1.w, h.w, l.w);
}

// ---------------- one-shot split of all 7 fp32 tensors ----------------
__global__ __launch_bounds__(256) void split_all(
    const float* __restrict__ i0, const float* __restrict__ i1,
    const float* __restrict__ i2, const float* __restrict__ i3,
    const float* __restrict__ i4, const float* __restrict__ i5,
    const float* __restrict__ i6,
    __nv_bfloat16* __restrict__ h0, __nv_bfloat16* __restrict__ h1,
    __nv_bfloat16* __restrict__ h2, __nv_bfloat16* __restrict__ h3,
    __nv_bfloat16* __restrict__ h4, __nv_bfloat16* __restrict__ h5,
    __nv_bfloat16* __restrict__ h6,
    __nv_bfloat16* __restrict__ l0, __nv_bfloat16* __restrict__ l1,
    __nv_bfloat16* __restrict__ l2, __nv_bfloat16* __restrict__ l3,
    __nv_bfloat16* __restrict__ l4, __nv_bfloat16* __restrict__ l5,
    __nv_bfloat16* __restrict__ l6)
{
    const int t = blockIdx.y;
    const int n = (t < 3) ? BS_*D_ : D_*D_;
    int i = (blockIdx.x * 256 + threadIdx.x) * 4;
    if (i >= n) return;
    const float* in = (t==0)?i0:(t==1)?i1:(t==2)?i2:(t==3)?i3:(t==4)?i4:(t==5)?i5:i6;
    __nv_bfloat16* hi = (t==0)?h0:(t==1)?h1:(t==2)?h2:(t==3)?h3:(t==4)?h4:(t==5)?h5:h6;
    __nv_bfloat16* lo = (t==0)?l0:(t==1)?l1:(t==2)?l2:(t==3)?l3:(t==4)?l4:(t==5)?l5:l6;
    float4 x = *reinterpret_cast<const float4*>(in + i);
    uint32_t a0, b0, a1, b1;
    split2(x.x, x.y, a0, b0);
    split2(x.z, x.w, a1, b1);
    *reinterpret_cast<uint2*>(hi + i) = make_uint2(a0, a1);
    *reinterpret_cast<uint2*>(lo + i) = make_uint2(b0, b1);
}

// ---------------- fold 16 partial sums per row -> 1/sum ----------------
__global__ __launch_bounds__(256) void reduce_inv(
    const float* __restrict__ ps, float* __restrict__ inv)
{
    int r = blockIdx.x * 256 + threadIdx.x;
    const float* p = ps + (long)r * NTILE_;
    float s = 0.0f;
#pragma unroll
    for (int j = 0; j < NTILE_; j++) s += p[j];
    inv[r] = 1.0f / s;
}

// ===========================================================================
// Shared GEMM machinery: BM=128, BN=128, BK=32, 8 warps, 2-stage cp.async,
// occupancy 2, 80B padded rows.
// ===========================================================================
#define GEMM_CONSTS \
    constexpr int BM = 128, BN = 128, BK = 32; \
    constexpr int ROWB = 80; \
    constexpr int ATILE = BM * ROWB; \
    constexpr int BTILE = BN * ROWB; \
    constexpr int STAGE = 2 * ATILE + 2 * BTILE; \
    constexpr int WARPS_M = 2, WARPS_N = 4; \
    constexpr int MT = 4, NT = 4; \
    (void)sizeof(char[WARPS_M + WARPS_N]);

#define GEMM_ISSUE(st, Ah_p, Al_p, Bh_p, Bl_p, kt) do { \
    _Pragma("unroll") \
    for (int i_ = 0; i_ < 2; i_++) { \
        int row_ = l_row + i_ * 64; \
        long g_ = (long)(m0 + row_) * lda + (kt) + l_c8 * 8; \
        uint32_t o_ = so + i_ * 64 * ROWB; \
        cp_async16((st) + 0     + o_, (Ah_p) + g_); \
        cp_async16((st) + ATILE + o_, (Al_p) + g_); \
    } \
    _Pragma("unroll") \
    for (int i_ = 0; i_ < 2; i_++) { \
        int row_ = l_row + i_ * 64; \
        long g_ = (long)(n0 + row_) * ldb + (kt) + l_c8 * 8; \
        uint32_t o_ = so + i_ * 64 * ROWB; \
        cp_async16((st) + 2*ATILE         + o_, (Bh_p) + g_); \
        cp_async16((st) + 2*ATILE + BTILE + o_, (Bl_p) + g_); \
    } \
} while(0)

#define GEMM_COMPUTE(st) do { \
    const uint32_t a_row_ = m_warp + (lane & 15); \
    const uint32_t a_k8_  = (lane >> 4) * 16; \
    const uint32_t b_row_ = n_warp + (lane & 7) + ((lane >> 4) & 1) * 8; \
    const uint32_t b_k8_  = ((lane >> 3) & 1) * 16; \
    _Pragma("unroll") \
    for (int ks_ = 0; ks_ < 2; ks_++) { \
        const uint32_t kb_ = ks_ * 32; \
        uint32_t ah_[MT][4], al_[MT][4]; \
        _Pragma("unroll") \
        for (int im_ = 0; im_ < MT; im_++) { \
            uint32_t ad_ = (st) + (a_row_ + im_ * 16) * ROWB + kb_ + a_k8_; \
            ldmat_x4(ah_[im_][0], ah_[im_][1], ah_[im_][2], ah_[im_][3], ad_); \
            ad_ += ATILE; \
            ldmat_x4(al_[im_][0], al_[im_][1], al_[im_][2], al_[im_][3], ad_); \
        } \
        uint32_t bh_[NT][2], bl_[NT][2]; \
        _Pragma("unroll") \
        for (int j2_ = 0; j2_ < NT/2; j2_++) { \
            uint32_t ad_ = (st) + 2*ATILE + (b_row_ + j2_ * 16) * ROWB + kb_ + b_k8_; \
            ldmat_x4(bh_[j2_*2][0], bh_[j2_*2][1], bh_[j2_*2+1][0], bh_[j2_*2+1][1], ad_); \
            ad_ += BTILE; \
            ldmat_x4(bl_[j2_*2][0], bl_[j2_*2][1], bl_[j2_*2+1][0], bl_[j2_*2+1][1], ad_); \
        } \
        _Pragma("unroll") \
        for (int im_ = 0; im_ < MT; im_++) \
        _Pragma("unroll") \
        for (int jn_ = 0; jn_ < NT; jn_++) { \
            float* d_ = acc[im_][jn_]; \
            mma_bf16(d_[0], d_[1], d_[2], d_[3], \
                     ah_[im_][0], ah_[im_][1], ah_[im_][2], ah_[im_][3], \
                     bh_[jn_][0], bh_[jn_][1]); \
            mma_bf16(d_[0], d_[1], d_[2], d_[3], \
                     ah_[im_][0], ah_[im_][1], ah_[im_][2], ah_[im_][3], \
                     bl_[jn_][0], bl_[jn_][1]); \
            mma_bf16(d_[0], d_[1], d_[2], d_[3], \
                     al_[im_][0], al_[im_][1], al_[im_][2], al_[im_][3], \
                     bh_[jn_][0], bh_[jn_][1]); \
        } \
    } \
} while(0)

#define GEMM_MAINLOOP(Ah_p, Al_p, Bh_p, Bl_p) do { \
    const int NI_ = K / BK; \
    GEMM_ISSUE(sbase, Ah_p, Al_p, Bh_p, Bl_p, 0); \
    CP_COMMIT(); \
    if (NI_ > 1) GEMM_ISSUE(sbase + STAGE, Ah_p, Al_p, Bh_p, Bl_p, BK); \
    CP_COMMIT(); \
    for (int it_ = 0; it_ < NI_; it_++) { \
        CP_WAIT1(); \
        __syncthreads(); \
        GEMM_COMPUTE(sbase + (it_ & 1) * STAGE); \
        __syncthreads(); \
        if (it_ + 2 < NI_) \
            GEMM_ISSUE(sbase + (it_ & 1) * STAGE, Ah_p, Al_p, Bh_p, Bl_p, (it_ + 2) * BK); \
        CP_COMMIT(); \
    } \
} while(0)

#define GEMM_PREAMBLE \
    GEMM_CONSTS \
    extern __shared__ char smem[]; \
    const uint32_t sbase = smem_u32(smem); \
    const int tid  = threadIdx.x; \
    const int lane = tid & 31; \
    const int wid  = tid >> 5; \
    const int m_warp = (wid % WARPS_M) * (BM / WARPS_M); \
    const int n_warp = (wid / WARPS_M) * (BN / WARPS_N); \
    const int l_row = tid >> 2; \
    const int l_c8  = tid & 3; \
    const uint32_t so = l_row * ROWB + l_c8 * 16; \
    float acc[MT][NT][4]; \
    _Pragma("unroll") \
    for (int i_ = 0; i_ < MT; i_++) \
    _Pragma("unroll") \
    for (int j_ = 0; j_ < NT; j_++) \
    _Pragma("unroll") \
    for (int r_ = 0; r_ < 4; r_++) acc[i_][j_][r_] = 0.0f;

// ---------------------------------------------------------------------------
// Merged Q/K/V projection GEMM (round-8, unchanged).
// ---------------------------------------------------------------------------
__global__ __launch_bounds__(256, 2) void mma_gemm_qkv(
    const __nv_bfloat16* __restrict__ iQh, const __nv_bfloat16* __restrict__ iQl,
    const __nv_bfloat16* __restrict__ iKh, const __nv_bfloat16* __restrict__ iKl,
    const __nv_bfloat16* __restrict__ iVh, const __nv_bfloat16* __restrict__ iVl,
    const __nv_bfloat16* __restrict__ wqh, const __nv_bfloat16* __restrict__ wql,
    const __nv_bfloat16* __restrict__ wkh, const __nv_bfloat16* __restrict__ wkl,
    const __nv_bfloat16* __restrict__ wvh, const __nv_bfloat16* __restrict__ wvl,
    __nv_bfloat16* __restrict__ qh, __nv_bfloat16* __restrict__ ql,
    __nv_bfloat16* __restrict__ kh, __nv_bfloat16* __restrict__ kl,
    __nv_bfloat16* __restrict__ vth, __nv_bfloat16* __restrict__ vtl)
{
    GEMM_PREAMBLE
    const int K = D_, lda = D_, ldb = D_, ldc = D_;
    const int m0 = blockIdx.y * BM;
    const int n0 = blockIdx.x * BN;
    const int proj = blockIdx.z;

    const __nv_bfloat16* A_h = (proj==0) ? iQh : (proj==1) ? iKh : iVh;
    const __nv_bfloat16* A_l = (proj==0) ? iQl : (proj==1) ? iKl : iVl;
    const __nv_bfloat16* B_h = (proj==0) ? wqh : (proj==1) ? wkh : wvh;
    const __nv_bfloat16* B_l = (proj==0) ? wql : (proj==1) ? wkl : wvl;
    __nv_bfloat16* C_h = (proj==0) ? qh : (proj==1) ? kh : vth;
    __nv_bfloat16* C_l = (proj==0) ? ql : (proj==1) ? kl : vtl;

    GEMM_MAINLOOP(A_h, A_l, B_h, B_l);

    const int rbase = m0 + m_warp + (lane >> 2);
    const int cbase = n0 + n_warp + (lane & 3) * 2;
    if (proj < 2) {
#pragma unroll
        for (int im = 0; im < MT; im++)
#pragma unroll
            for (int jn = 0; jn < NT; jn++) {
                const float* d = acc[im][jn];
                int r0 = rbase + im * 16;
                int c  = cbase + jn * 8;
                uint32_t h, l;
                split2(d[0], d[1], h, l);
                long b0a = (long)r0 * ldc + c;
                *reinterpret_cast<uint32_t*>(C_h + b0a) = h;
                *reinterpret_cast<uint32_t*>(C_l + b0a) = l;
                split2(d[2], d[3], h, l);
                long b1a = (long)(r0 + 8) * ldc + c;
                *reinterpret_cast<uint32_t*>(C_h + b1a) = h;
                *reinterpret_cast<uint32_t*>(C_l + b1a) = l;
            }
    } else {
#pragma unroll
        for (int im = 0; im < MT; im++)
#pragma unroll
            for (int jn = 0; jn < NT; jn++) {
                const float* d = acc[im][jn];
                int r0 = rbase + im * 16;
                int c  = cbase + jn * 8;
#pragma unroll
                for (int e = 0; e < 4; e++) {
                    int m = r0 + (e >> 1) * 8;
                    int n = c + (e & 1);
                    float f = d[e];
                    __nv_bfloat16 hv = __float2bfloat16(f);
                    __nv_bfloat16 lv = __float2bfloat16(f - __bfloat162float(hv));
                    int b2 = m >> 11, s2 = m & (S_ - 1);
                    int hidx = n >> 6, hd = n & 63;
                    long addr = (((long)b2 * H_ + hidx) * HD_ + hd) * S_ + s2;
                    C_h[addr] = hv;
                    C_l[addr] = lv;
                }
            }
    }
}

// ---------------------------------------------------------------------------
// Generic batched GEMM, fp32 epilogue (*alpha). Used for the final GEMM.
// ---------------------------------------------------------------------------
__global__ __launch_bounds__(256, 2) void mma_gemm_f32(
    const __nv_bfloat16* __restrict__ Ah, const __nv_bfloat16* __restrict__ Al,
    const __nv_bfloat16* __restrict__ Bh, const __nv_bfloat16* __restrict__ Bl,
    float* __restrict__ C,
    int K, int lda, int ldb, int ldc,
    long offAb, long offAh_, long offBb, long offBh_, long offCb, long offCh_,
    int Hdiv, float alpha)
{
    GEMM_PREAMBLE
    const int z = blockIdx.z;
    const int bb = z / Hdiv, hh = z % Hdiv;
    const __nv_bfloat16* A_h = Ah + (long)bb * offAb + (long)hh * offAh_;
    const __nv_bfloat16* A_l = Al + (long)bb * offAb + (long)hh * offAh_;
    const __nv_bfloat16* B_h = Bh + (long)bb * offBb + (long)hh * offBh_;
    const __nv_bfloat16* B_l = Bl + (long)bb * offBb + (long)hh * offBh_;
    const long coff = (long)bb * offCb + (long)hh * offCh_;
    const int m0 = blockIdx.y * BM;
    const int n0 = blockIdx.x * BN;

    GEMM_MAINLOOP(A_h, A_l, B_h, B_l);

    const int rbase = m0 + m_warp + (lane >> 2);
    const int cbase = n0 + n_warp + (lane & 3) * 2;
#pragma unroll
    for (int im = 0; im < MT; im++)
#pragma unroll
        for (int jn = 0; jn < NT; jn++) {
            const float* d = acc[im][jn];
            int r0 = rbase + im * 16;
            int c  = cbase + jn * 8;
            *reinterpret_cast<float2*>(C + coff + (long)r0 * ldc + c) =
                make_float2(d[0] * alpha, d[1] * alpha);
            *reinterpret_cast<float2*>(C + coff + (long)(r0 + 8) * ldc + c) =
                make_float2(d[2] * alpha, d[3] * alpha);
        }
}

// ---------------------------------------------------------------------------
// Scores GEMM, two modes.
//   MODE 0: compute exp(alpha*acc), emit per-block row-sum partials ONLY
//           (no 537MB C write).
//   MODE 1: recompute, write exp(alpha*acc) * Inv[row] = final softmax to C.
// ---------------------------------------------------------------------------
template <int MODE>
__global__ __launch_bounds__(256, 2) void mma_gemm_scores(
    const __nv_bfloat16* __restrict__ Ah, const __nv_bfloat16* __restrict__ Al,
    const __nv_bfloat16* __restrict__ Bh, const __nv_bfloat16* __restrict__ Bl,
    float* __restrict__ C, float* __restrict__ PS, const float* __restrict__ Inv,
    int K, int lda, int ldb, int ldc,
    long offAb, long offAh_, long offBb, long offBh_, long offCb, long offCh_,
    int Hdiv, float alpha)
{
    GEMM_PREAMBLE
    const int z = blockIdx.z;
    const int bb = z / Hdiv, hh = z % Hdiv;
    const __nv_bfloat16* A_h = Ah + (long)bb * offAb + (long)hh * offAh_;
    const __nv_bfloat16* A_l = Al + (long)bb * offAb + (long)hh * offAh_;
    const __nv_bfloat16* B_h = Bh + (long)bb * offBb + (long)hh * offBh_;
    const __nv_bfloat16* B_l = Bl + (long)bb * offBb + (long)hh * offBh_;
    const long coff = (long)bb * offCb + (long)hh * offCh_;
    const int m0 = blockIdx.y * BM;
    const int n0 = blockIdx.x * BN;

    GEMM_MAINLOOP(A_h, A_l, B_h, B_l);

    const int rbase = m0 + m_warp + (lane >> 2);
    const int cbase = n0 + n_warp + (lane & 3) * 2;

    if (MODE == 0) {
        // exp + row-sum partials, no C write
        float s0[MT], s1[MT];
#pragma unroll
        for (int im = 0; im < MT; im++) { s0[im] = 0.0f; s1[im] = 0.0f; }
#pragma unroll
        for (int im = 0; im < MT; im++)
#pragma unroll
            for (int jn = 0; jn < NT; jn++) {
                const float* d = acc[im][jn];
                s0[im] += __expf(d[0] * alpha) + __expf(d[1] * alpha);
                s1[im] += __expf(d[2] * alpha) + __expf(d[3] * alpha);
            }
        __syncthreads();
        float* sm_ps = reinterpret_cast<float*>(smem);   // [WARPS_N][BM]
        const int nw = wid / WARPS_M;
#pragma unroll
        for (int im = 0; im < MT; im++) {
            float a0 = s0[im], a1 = s1[im];
            a0 += __shfl_xor_sync(0xFFFFFFFFu, a0, 1);
            a0 += __shfl_xor_sync(0xFFFFFFFFu, a0, 2);
            a1 += __shfl_xor_sync(0xFFFFFFFFu, a1, 1);
            a1 += __shfl_xor_sync(0xFFFFFFFFu, a1, 2);
            if ((lane & 3) == 0) {
                int rl = m_warp + im * 16 + (lane >> 2);
                sm_ps[nw * BM + rl]     = a0;
                sm_ps[nw * BM + rl + 8] = a1;
            }
        }
        __syncthreads();
        if (tid < BM) {
            float s = sm_ps[tid];
#pragma unroll
            for (int w = 1; w < WARPS_N; w++) s += sm_ps[w * BM + tid];
            PS[((long)z * S_ + m0 + tid) * NTILE_ + blockIdx.x] = s;
        }
    } else {
        // write final softmax = exp * inv directly
        const long zs = (long)z * S_;
#pragma unroll
        for (int im = 0; im < MT; im++) {
            const int r0 = rbase + im * 16;
            const float ivA = Inv[zs + r0];
            const float ivB = Inv[zs + r0 + 8];
#pragma unroll
            for (int jn = 0; jn < NT; jn++) {
                const float* d = acc[im][jn];
                int c = cbase + jn * 8;
                *reinterpret_cast<float2*>(C + coff + (long)r0 * ldc + c) =
                    make_float2(__expf(d[0] * alpha) * ivA, __expf(d[1] * alpha) * ivA);
                *reinterpret_cast<float2*>(C + coff + (long)(r0 + 8) * ldc + c) =
                    make_float2(__expf(d[2] * alpha) * ivB, __expf(d[3] * alpha) * ivB);
            }
        }
    }
}

// ---------------------------------------------------------------------------
// AV GEMM (round-8): A = normalized fp32 weights (split on load), B bf16.
// BM=128, BN=64, BK=32, occupancy 2. split-bf16 store.
// ---------------------------------------------------------------------------
__global__ __launch_bounds__(256, 2) void mma_gemm_av(
    const float* __restrict__ Afp,
    const __nv_bfloat16* __restrict__ Bh, const __nv_bfloat16* __restrict__ Bl,
    __nv_bfloat16* __restrict__ Chi, __nv_bfloat16* __restrict__ Clo,
    int K, int lda, int ldb, int ldc,
    long offAb, long offAh_, long offBb, long offBh_, long offCb, long offCh_,
    int Hdiv)
{
    constexpr int BM = 128, BN = 64, BK = 32;
    constexpr int ROWB = 80;
    constexpr int ATILE = BM * ROWB;
    constexpr int BTILE = BN * ROWB;
    constexpr int STAGE = 2 * ATILE + 2 * BTILE;
    constexpr int AF4 = 2, BF4 = 1;
    constexpr int WARPS_M = 4, WARPS_N = 2;
    constexpr int MT = 2, NT = 4;

    extern __shared__ char smem[];
    const uint32_t sbase = smem_u32(smem);

    const int tid  = threadIdx.x;
    const int lane = tid & 31;
    const int wid  = tid >> 5;

    const int z = blockIdx.z;
    const int bb = z / Hdiv, hh = z % Hdiv;
    const float* A = Afp + (long)bb * offAb + (long)hh * offAh_;
    const __nv_bfloat16* B_h = Bh + (long)bb * offBb + (long)hh * offBh_;
    const __nv_bfloat16* B_l = Bl + (long)bb * offBb + (long)hh * offBh_;
    const long coff = (long)bb * offCb + (long)hh * offCh_;

    const int m0 = blockIdx.y * BM;
    const int n0 = blockIdx.x * BN;

    const int m_warp = (wid % WARPS_M) * (BM / WARPS_M);
    const int n_warp = (wid / WARPS_M) * (BN / WARPS_N);

    const uint32_t OFF_AH = 0, OFF_AL = ATILE, OFF_BH = 2*ATILE, OFF_BL = 2*ATILE + BTILE;

    float acc[MT][NT][4];
#pragma unroll
    for (int i = 0; i < MT; i++)
#pragma unroll
        for (int j = 0; j < NT; j++)
#pragma unroll
            for (int r = 0; r < 4; r++) acc[i][j][r] = 0.0f;

    uint4 rAh[AF4], rAl[AF4], rBh[BF4], rBl[BF4];

    auto gload = [&](int it) {
        const int kt = it * BK;
#pragma unroll
        for (int i = 0; i < AF4; i++) {
            int f4 = tid + i * 256;
            int row = f4 >> 2, c8 = f4 & 3;
            long g = (long)(m0 + row) * lda + kt + c8 * 8;
            float4 x0 = *reinterpret_cast<const float4*>(A + g);
            float4 x1 = *reinterpret_cast<const float4*>(A + g + 4);
            split8(x0, x1, rAh[i], rAl[i]);
        }
#pragma unroll
        for (int i = 0; i < BF4; i++) {
            int f4 = tid + i * 256;
            int row = f4 >> 2, c8 = f4 & 3;
            long g = (long)(n0 + row) * ldb + kt + c8 * 8;
            rBh[i] = *reinterpret_cast<const uint4*>(B_h + g);
            rBl[i] = *reinterpret_cast<const uint4*>(B_l + g);
        }
    };

    auto sstore = [&](int buf) {
        char* st = smem + buf * STAGE;
#pragma unroll
        for (int i = 0; i < AF4; i++) {
            int f4 = tid + i * 256;
            int row = f4 >> 2, c8 = f4 & 3;
            uint32_t o = row * ROWB + c8 * 16;
            *reinterpret_cast<uint4*>(st + OFF_AH + o) = rAh[i];
            *reinterpret_cast<uint4*>(st + OFF_AL + o) = rAl[i];
        }
#pragma unroll
        for (int i = 0; i < BF4; i++) {
            int f4 = tid + i * 256;
            int row = f4 >> 2, c8 = f4 & 3;
            uint32_t o = row * ROWB + c8 * 16;
            *reinterpret_cast<uint4*>(st + OFF_BH + o) = rBh[i];
            *reinterpret_cast<uint4*>(st + OFF_BL + o) = rBl[i];
        }
    };

    auto compute = [&](int buf) {
        const uint32_t st = sbase + buf * STAGE;
        const uint32_t a_row = m_warp + (lane & 15);
        const uint32_t a_k8  = (lane >> 4) * 16;
        const uint32_t b_row = n_warp + (lane & 7) + ((lane >> 4) & 1) * 8;
        const uint32_t b_k8  = ((lane >> 3) & 1) * 16;
#pragma unroll
        for (int ks = 0; ks < 2; ks++) {
            const uint32_t kbyte = ks * 32;
            uint32_t ah[MT][4], al[MT][4];
#pragma unroll
            for (int im = 0; im < MT; im++) {
                uint32_t addr = st + OFF_AH + (a_row + im * 16) * ROWB + kbyte + a_k8;
                ldmat_x4(ah[im][0], ah[im][1], ah[im][2], ah[im][3], addr);
                addr += ATILE;
                ldmat_x4(al[im][0], al[im][1], al[im][2], al[im][3], addr);
            }
            uint32_t bh[NT][2], bl[NT][2];
#pragma unroll
            for (int j2 = 0; j2 < NT / 2; j2++) {
                uint32_t addr = st + OFF_BH + (b_row + j2 * 16) * ROWB + kbyte + b_k8;
                ldmat_x4(bh[j2*2][0], bh[j2*2][1], bh[j2*2+1][0], bh[j2*2+1][1], addr);
                addr += BTILE;
                ldmat_x4(bl[j2*2][0], bl[j2*2][1], bl[j2*2+1][0], bl[j2*2+1][1], addr);
            }
#pragma unroll
            for (int im = 0; im < MT; im++)
#pragma unroll
                for (int jn = 0; jn < NT; jn++) {
                    float* d = acc[im][jn];
                    mma_bf16(d[0], d[1], d[2], d[3],
                             ah[im][0], ah[im][1], ah[im][2], ah[im][3],
                             bh[jn][0], bh[jn][1]);
                    mma_bf16(d[0], d[1], d[2], d[3],
                             ah[im][0], ah[im][1], ah[im][2], ah[im][3],
                             bl[jn][0], bl[jn][1]);
                    mma_bf16(d[0], d[1], d[2], d[3],
                             al[im][0], al[im][1], al[im][2], al[im][3],
                             bh[jn][0], bh[jn][1]);
                }
        }
    };

    const int NI = K / BK;
    gload(0);
    sstore(0);
    __syncthreads();
    int buf = 0;
    for (int it = 1; it < NI; it++) {
        gload(it);
        compute(buf);
        sstore(buf ^ 1);
        __syncthreads();
        buf ^= 1;
    }
    compute(buf);

    const int rbase = m0 + m_warp + (lane >> 2);
    const int cbase = n0 + n_warp + (lane & 3) * 2;
#pragma unroll
    for (int im = 0; im < MT; im++) {
#pragma unroll
        for (int jn = 0; jn < NT; jn++) {
            const float* d = acc[im][jn];
            int r0 = rbase + im * 16;
            int c  = cbase + jn * 8;
            uint32_t h, l;
            split2(d[0], d[1], h, l);
            long b0a = coff + (long)r0 * ldc + c;
            *reinterpret_cast<uint32_t*>(Chi + b0a) = h;
            *reinterpret_cast<uint32_t*>(Clo + b0a) = l;
            split2(d[2], d[3], h, l);
            long b1a = coff + (long)(r0 + 8) * ldc + c;
            *reinterpret_cast<uint32_t*>(Chi + b1a) = h;
            *reinterpret_cast<uint32_t*>(Clo + b1a) = l;
        }
    }
}

// ---------------------------------------------------------------------------
extern "C" void kernel_launch(void* const* d_in, const int* in_sizes, int n_in,
                              void* d_out, int out_size)
{
    const float* Q  = (const float*)d_in[0];
    const float* K  = (const float*)d_in[1];
    const float* V  = (const float*)d_in[2];
    const float* Wq = (const float*)d_in[3];
    const float* Wk = (const float*)d_in[4];
    const float* Wv = (const float*)d_in[5];
    const float* Wo = (const float*)d_in[6];

    float* out = (float*)d_out;
    float* final_out = out;                       // [B,S,D]
    float* weights   = out + (long)B_ * S_ * D_;  // [B,H,S,S]

    __nv_bfloat16 *iQh,*iQl,*iKh,*iKl,*iVh,*iVl;
    __nv_bfloat16 *wqh,*wql,*wkh,*wkl,*wvh,*wvl,*woh,*wol;
    __nv_bfloat16 *qh,*ql,*kh,*kl,*vth,*vtl,*cath,*catl;
    float *psum, *inv;
    cudaGetSymbolAddress((void**)&iQh, g_iQh); cudaGetSymbolAddress((void**)&iQl, g_iQl);
    cudaGetSymbolAddress((void**)&iKh, g_iKh); cudaGetSymbolAddress((void**)&iKl, g_iKl);
    cudaGetSymbolAddress((void**)&iVh, g_iVh); cudaGetSymbolAddress((void**)&iVl, g_iVl);
    cudaGetSymbolAddress((void**)&wqh, g_wqh); cudaGetSymbolAddress((void**)&wql, g_wql);
    cudaGetSymbolAddress((void**)&wkh, g_wkh); cudaGetSymbolAddress((void**)&wkl, g_wkl);
    cudaGetSymbolAddress((void**)&wvh, g_wvh); cudaGetSymbolAddress((void**)&wvl, g_wvl);
    cudaGetSymbolAddress((void**)&woh, g_woh); cudaGetSymbolAddress((void**)&wol, g_wol);
    cudaGetSymbolAddress((void**)&qh,  g_qh);  cudaGetSymbolAddress((void**)&ql,  g_ql);
    cudaGetSymbolAddress((void**)&kh,  g_kh);  cudaGetSymbolAddress((void**)&kl,  g_kl);
    cudaGetSymbolAddress((void**)&vth, g_vth); cudaGetSymbolAddress((void**)&vtl, g_vtl);
    cudaGetSymbolAddress((void**)&cath,g_cath);cudaGetSymbolAddress((void**)&catl,g_catl);
    cudaGetSymbolAddress((void**)&psum,g_psum);cudaGetSymbolAddress((void**)&inv, g_inv);

    constexpr int ROWB = 80;
    constexpr int SM_G  = 2 * (2 * 128 * ROWB + 2 * 128 * ROWB);  // 81920
    constexpr int SM_AV = 2 * (2 * 128 * ROWB + 2 * 64 * ROWB);   // 61440

    cudaFuncSetAttribute(mma_gemm_qkv,       cudaFuncAttributeMaxDynamicSharedMemorySize, SM_G);
    cudaFuncSetAttribute(mma_gemm_f32,       cudaFuncAttributeMaxDynamicSharedMemorySize, SM_G);
    cudaFuncSetAttribute(mma_gemm_scores<0>, cudaFuncAttributeMaxDynamicSharedMemorySize, SM_G);
    cudaFuncSetAttribute(mma_gemm_scores<1>, cudaFuncAttributeMaxDynamicSharedMemorySize, SM_G);
    cudaFuncSetAttribute(mma_gemm_av,        cudaFuncAttributeMaxDynamicSharedMemorySize, SM_AV);

    // 0) split all fp32 inputs into bf16 hi/lo
    {
        dim3 g(BS_*D_/1024, 7, 1);
        split_all<<<g, 256>>>(Q, K, V, Wq, Wk, Wv, Wo,
                              iQh, iKh, iVh, wqh, wkh, wvh, woh,
                              iQl, iKl, iVl, wql, wkl, wvl, wol);
    }

    // 1) merged projections
    {
        dim3 g(D_/128, BS_/128, 3);
        mma_gemm_qkv<<<g, 256, SM_G>>>(iQh, iQl, iKh, iKl, iVh, iVl,
                                       wqh, wql, wkh, wkl, wvh, wvl,
                                       qh, ql, kh, kl, vth, vtl);
    }

    // 2a) scores pass 1: exp row sums only (no 537MB write)
    {
        dim3 g(S_/128, S_/128, B_*H_);
        mma_gemm_scores<0><<<g, 256, SM_G>>>(qh, ql, kh, kl,
            nullptr, psum, nullptr,
            HD_, D_, D_, S_,
            (long)S_*D_, (long)HD_, (long)S_*D_, (long)HD_,
            (long)H_*S_*S_, (long)S_*S_, H_, 0.125f);
    }

    // 2b) fold partials -> inv row sums
    reduce_inv<<<NROWS_/256, 256>>>(psum, inv);

    // 2c) scores pass 2: recompute, write final softmax = exp * inv
    {
        dim3 g(S_/128, S_/128, B_*H_);
        mma_gemm_scores<1><<<g, 256, SM_G>>>(qh, ql, kh, kl,
            weights, nullptr, inv,
            HD_, D_, D_, S_,
            (long)S_*D_, (long)HD_, (long)S_*D_, (long)HD_,
            (long)H_*S_*S_, (long)S_*S_, H_, 0.125f);
    }

    // 3) cat = softmax @ v (reads normalized weights, split on load)
    {
        dim3 g(1, S_/128, B_*H_);
        mma_gemm_av<<<g, 256, SM_AV>>>(weights, vth, vtl,
            cath, catl,
            S_, S_, S_, D_,
            (long)H_*S_*S_, (long)S_*S_,
            (long)H_*HD_*S_, (long)HD_*S_,
            (long)S_*D_, (long)HD_, H_);
    }

    // 4) final = cat @ Wo^T (fp32 out)
    {
        dim3 g(D_/128, BS_/128, 1);
        mma_gemm_f32<<<g, 256, SM_G>>>(cath, catl, woh, wol, final_out,
            D_, D_, D_, D_, 0,0,0,0,0,0, 1, 1.0f);
    }
}

// round 13
// speedup vs baseline: 1.0216x; 1.0216x over previous
#include <cuda_runtime.h>
#include <cuda_bf16.h>
#include <stdint.h>
#include <math.h>

#define B_ 2
#define S_ 2048
#define D_ 1024
#define H_ 16
#define HD_ 64
#define BS_ (B_*S_)

// ---------------- bf16 split scratch ----------------
__device__ __nv_bfloat16 g_iQh[BS_*D_], g_iQl[BS_*D_];
__device__ __nv_bfloat16 g_iKh[BS_*D_], g_iKl[BS_*D_];
__device__ __nv_bfloat16 g_iVh[BS_*D_], g_iVl[BS_*D_];
__device__ __nv_bfloat16 g_wqh[D_*D_], g_wql[D_*D_];
__device__ __nv_bfloat16 g_wkh[D_*D_], g_wkl[D_*D_];
__device__ __nv_bfloat16 g_wvh[D_*D_], g_wvl[D_*D_];
__device__ __nv_bfloat16 g_woh[D_*D_], g_wol[D_*D_];
__device__ __nv_bfloat16 g_qh[BS_*D_], g_ql[BS_*D_];
__device__ __nv_bfloat16 g_kh[BS_*D_], g_kl[BS_*D_];
__device__ __nv_bfloat16 g_vth[BS_*D_], g_vtl[BS_*D_];   // [B,H,HD,S]
__device__ __nv_bfloat16 g_cath[BS_*D_], g_catl[BS_*D_]; // [B,S,D]

// ---------------- helpers ----------------
__device__ __forceinline__ uint32_t smem_u32(const void* p){
    uint32_t a;
    asm("{ .reg .u64 t; cvta.to.shared.u64 t, %1; cvt.u32.u64 %0, t; }" : "=r"(a) : "l"(p));
    return a;
}
__device__ __forceinline__ void cp_async16(uint32_t saddr, const void* g){
    asm volatile("cp.async.cg.shared.global [%0], [%1], 16;" :: "r"(saddr), "l"(g));
}
#define CP_COMMIT() asm volatile("cp.async.commit_group;" ::: "memory")
#define CP_WAIT1()  asm volatile("cp.async.wait_group 1;"  ::: "memory")

__device__ __forceinline__ void ldmat_x4(uint32_t& r0, uint32_t& r1, uint32_t& r2,
                                         uint32_t& r3, uint32_t addr){
    asm volatile("ldmatrix.sync.aligned.m8n8.x4.shared.b16 {%0,%1,%2,%3}, [%4];"
        : "=r"(r0), "=r"(r1), "=r"(r2), "=r"(r3) : "r"(addr));
}
__device__ __forceinline__ void mma_bf16(float& d0, float& d1, float& d2, float& d3,
                                         uint32_t a0, uint32_t a1, uint32_t a2, uint32_t a3,
                                         uint32_t b0, uint32_t b1){
    asm volatile("mma.sync.aligned.m16n8k16.row.col.f32.bf16.bf16.f32 "
        "{%0,%1,%2,%3}, {%4,%5,%6,%7}, {%8,%9}, {%0,%1,%2,%3};"
        : "+f"(d0), "+f"(d1), "+f"(d2), "+f"(d3)
        : "r"(a0), "r"(a1), "r"(a2), "r"(a3), "r"(b0), "r"(b1));
}
__device__ __forceinline__ uint32_t pack_bf16x2(float a, float b){
    __nv_bfloat162 v = __floats2bfloat162_rn(a, b);
    return *reinterpret_cast<uint32_t*>(&v);
}
__device__ __forceinline__ void split2(float a, float b, uint32_t& h, uint32_t& l){
    __nv_bfloat16 ha = __float2bfloat16(a), hb = __float2bfloat16(b);
    h = ((uint32_t)__bfloat16_as_ushort(ha)) | (((uint32_t)__bfloat16_as_ushort(hb)) << 16);
    l = pack_bf16x2(a - __bfloat162float(ha), b - __bfloat162float(hb));
}
__device__ __forceinline__ void split8(const float4& x0, const float4& x1,
                                       uint4& h, uint4& l){
    split2(x0.x, x0.y, h.x, l.x);
    split2(x0.z, x0.w, h.y, l.y);
    split2(x1.x, x1.y, h.z, l.z);
    split2(x1.z, x1.w, h.w, l.w);
}

// ---------------- one-shot split of all 7 fp32 tensors ----------------
__global__ __launch_bounds__(256) void split_all(
    const float* __restrict__ i0, const float* __restrict__ i1,
    const float* __restrict__ i2, const float* __restrict__ i3,
    const float* __restrict__ i4, const float* __restrict__ i5,
    const float* __restrict__ i6,
    __nv_bfloat16* __restrict__ h0, __nv_bfloat16* __restrict__ h1,
    __nv_bfloat16* __restrict__ h2, __nv_bfloat16* __restrict__ h3,
    __nv_bfloat16* __restrict__ h4, __nv_bfloat16* __restrict__ h5,
    __nv_bfloat16* __restrict__ h6,
    __nv_bfloat16* __restrict__ l0, __nv_bfloat16* __restrict__ l1,
    __nv_bfloat16* __restrict__ l2, __nv_bfloat16* __restrict__ l3,
    __nv_bfloat16* __restrict__ l4, __nv_bfloat16* __restrict__ l5,
    __nv_bfloat16* __restrict__ l6)
{
    const int t = blockIdx.y;
    const int n = (t < 3) ? BS_*D_ : D_*D_;
    int i = (blockIdx.x * 256 + threadIdx.x) * 4;
    if (i >= n) return;
    const float* in = (t==0)?i0:(t==1)?i1:(t==2)?i2:(t==3)?i3:(t==4)?i4:(t==5)?i5:i6;
    __nv_bfloat16* hi = (t==0)?h0:(t==1)?h1:(t==2)?h2:(t==3)?h3:(t==4)?h4:(t==5)?h5:h6;
    __nv_bfloat16* lo = (t==0)?l0:(t==1)?l1:(t==2)?l2:(t==3)?l3:(t==4)?l4:(t==5)?l5:l6;
    float4 x = *reinterpret_cast<const float4*>(in + i);
    uint32_t a0, b0, a1, b1;
    split2(x.x, x.y, a0, b0);
    split2(x.z, x.w, a1, b1);
    *reinterpret_cast<uint2*>(hi + i) = make_uint2(a0, a1);
    *reinterpret_cast<uint2*>(lo + i) = make_uint2(b0, b1);
}

// ===========================================================================
// Shared GEMM machinery: BM=128, BN=128, BK=32, 8 warps, 2-stage cp.async,
// occupancy 2, 80B padded rows.
// ===========================================================================
#define GEMM_CONSTS \
    constexpr int BM = 128, BN = 128, BK = 32; \
    constexpr int ROWB = 80; \
    constexpr int ATILE = BM * ROWB; \
    constexpr int BTILE = BN * ROWB; \
    constexpr int STAGE = 2 * ATILE + 2 * BTILE; \
    constexpr int WARPS_M = 2, WARPS_N = 4; \
    constexpr int MT = 4, NT = 4; \
    (void)sizeof(char[WARPS_M + WARPS_N]);

#define GEMM_ISSUE(st, Ah_p, Al_p, Bh_p, Bl_p, kt) do { \
    _Pragma("unroll") \
    for (int i_ = 0; i_ < 2; i_++) { \
        int row_ = l_row + i_ * 64; \
        long g_ = (long)(m0 + row_) * lda + (kt) + l_c8 * 8; \
        uint32_t o_ = so + i_ * 64 * ROWB; \
        cp_async16((st) + 0     + o_, (Ah_p) + g_); \
        cp_async16((st) + ATILE + o_, (Al_p) + g_); \
    } \
    _Pragma("unroll") \
    for (int i_ = 0; i_ < 2; i_++) { \
        int row_ = l_row + i_ * 64; \
        long g_ = (long)(n0 + row_) * ldb + (kt) + l_c8 * 8; \
        uint32_t o_ = so + i_ * 64 * ROWB; \
        cp_async16((st) + 2*ATILE         + o_, (Bh_p) + g_); \
        cp_async16((st) + 2*ATILE + BTILE + o_, (Bl_p) + g_); \
    } \
} while(0)

#define GEMM_COMPUTE(st) do { \
    const uint32_t a_row_ = m_warp + (lane & 15); \
    const uint32_t a_k8_  = (lane >> 4) * 16; \
    const uint32_t b_row_ = n_warp + (lane & 7) + ((lane >> 4) & 1) * 8; \
    const uint32_t b_k8_  = ((lane >> 3) & 1) * 16; \
    _Pragma("unroll") \
    for (int ks_ = 0; ks_ < 2; ks_++) { \
        const uint32_t kb_ = ks_ * 32; \
        uint32_t ah_[MT][4], al_[MT][4]; \
        _Pragma("unroll") \
        for (int im_ = 0; im_ < MT; im_++) { \
            uint32_t ad_ = (st) + (a_row_ + im_ * 16) * ROWB + kb_ + a_k8_; \
            ldmat_x4(ah_[im_][0], ah_[im_][1], ah_[im_][2], ah_[im_][3], ad_); \
            ad_ += ATILE; \
            ldmat_x4(al_[im_][0], al_[im_][1], al_[im_][2], al_[im_][3], ad_); \
        } \
        uint32_t bh_[NT][2], bl_[NT][2]; \
        _Pragma("unroll") \
        for (int j2_ = 0; j2_ < NT/2; j2_++) { \
            uint32_t ad_ = (st) + 2*ATILE + (b_row_ + j2_ * 16) * ROWB + kb_ + b_k8_; \
            ldmat_x4(bh_[j2_*2][0], bh_[j2_*2][1], bh_[j2_*2+1][0], bh_[j2_*2+1][1], ad_); \
            ad_ += BTILE; \
            ldmat_x4(bl_[j2_*2][0], bl_[j2_*2][1], bl_[j2_*2+1][0], bl_[j2_*2+1][1], ad_); \
        } \
        _Pragma("unroll") \
        for (int im_ = 0; im_ < MT; im_++) \
        _Pragma("unroll") \
        for (int jn_ = 0; jn_ < NT; jn_++) { \
            float* d_ = acc[im_][jn_]; \
            mma_bf16(d_[0], d_[1], d_[2], d_[3], \
                     ah_[im_][0], ah_[im_][1], ah_[im_][2], ah_[im_][3], \
                     bh_[jn_][0], bh_[jn_][1]); \
            mma_bf16(d_[0], d_[1], d_[2], d_[3], \
                     ah_[im_][0], ah_[im_][1], ah_[im_][2], ah_[im_][3], \
                     bl_[jn_][0], bl_[jn_][1]); \
            mma_bf16(d_[0], d_[1], d_[2], d_[3], \
                     al_[im_][0], al_[im_][1], al_[im_][2], al_[im_][3], \
                     bh_[jn_][0], bh_[jn_][1]); \
        } \
    } \
} while(0)

#define GEMM_MAINLOOP(Ah_p, Al_p, Bh_p, Bl_p) do { \
    const int NI_ = K / BK; \
    GEMM_ISSUE(sbase, Ah_p, Al_p, Bh_p, Bl_p, 0); \
    CP_COMMIT(); \
    if (NI_ > 1) GEMM_ISSUE(sbase + STAGE, Ah_p, Al_p, Bh_p, Bl_p, BK); \
    CP_COMMIT(); \
    for (int it_ = 0; it_ < NI_; it_++) { \
        CP_WAIT1(); \
        __syncthreads(); \
        GEMM_COMPUTE(sbase + (it_ & 1) * STAGE); \
        __syncthreads(); \
        if (it_ + 2 < NI_) \
            GEMM_ISSUE(sbase + (it_ & 1) * STAGE, Ah_p, Al_p, Bh_p, Bl_p, (it_ + 2) * BK); \
        CP_COMMIT(); \
    } \
} while(0)

#define GEMM_PREAMBLE \
    GEMM_CONSTS \
    extern __shared__ char smem[]; \
    const uint32_t sbase = smem_u32(smem); \
    const int tid  = threadIdx.x; \
    const int lane = tid & 31; \
    const int wid  = tid >> 5; \
    const int m_warp = (wid % WARPS_M) * (BM / WARPS_M); \
    const int n_warp = (wid / WARPS_M) * (BN / WARPS_N); \
    const int l_row = tid >> 2; \
    const int l_c8  = tid & 3; \
    const uint32_t so = l_row * ROWB + l_c8 * 16; \
    float acc[MT][NT][4]; \
    _Pragma("unroll") \
    for (int i_ = 0; i_ < MT; i_++) \
    _Pragma("unroll") \
    for (int j_ = 0; j_ < NT; j_++) \
    _Pragma("unroll") \
    for (int r_ = 0; r_ < 4; r_++) acc[i_][j_][r_] = 0.0f;

// ---------------------------------------------------------------------------
// Merged Q/K/V projection GEMM. proj 0,1: direct split-bf16 store.
// proj 2: smem-transpose staging, then coalesced uint4 stores to [B,H,HD,S].
// ---------------------------------------------------------------------------
__global__ __launch_bounds__(256, 2) void mma_gemm_qkv(
    const __nv_bfloat16* __restrict__ iQh, const __nv_bfloat16* __restrict__ iQl,
    const __nv_bfloat16* __restrict__ iKh, const __nv_bfloat16* __restrict__ iKl,
    const __nv_bfloat16* __restrict__ iVh, const __nv_bfloat16* __restrict__ iVl,
    const __nv_bfloat16* __restrict__ wqh, const __nv_bfloat16* __restrict__ wql,
    const __nv_bfloat16* __restrict__ wkh, const __nv_bfloat16* __restrict__ wkl,
    const __nv_bfloat16* __restrict__ wvh, const __nv_bfloat16* __restrict__ wvl,
    __nv_bfloat16* __restrict__ qh, __nv_bfloat16* __restrict__ ql,
    __nv_bfloat16* __restrict__ kh, __nv_bfloat16* __restrict__ kl,
    __nv_bfloat16* __restrict__ vth, __nv_bfloat16* __restrict__ vtl)
{
    GEMM_PREAMBLE
    const int K = D_, lda = D_, ldb = D_, ldc = D_;
    const int m0 = blockIdx.y * BM;
    const int n0 = blockIdx.x * BN;
    const int proj = blockIdx.z;

    const __nv_bfloat16* A_h = (proj==0) ? iQh : (proj==1) ? iKh : iVh;
    const __nv_bfloat16* A_l = (proj==0) ? iQl : (proj==1) ? iKl : iVl;
    const __nv_bfloat16* B_h = (proj==0) ? wqh : (proj==1) ? wkh : wvh;
    const __nv_bfloat16* B_l = (proj==0) ? wql : (proj==1) ? wkl : wvl;
    __nv_bfloat16* C_h = (proj==0) ? qh : (proj==1) ? kh : vth;
    __nv_bfloat16* C_l = (proj==0) ? ql : (proj==1) ? kl : vtl;

    GEMM_MAINLOOP(A_h, A_l, B_h, B_l);

    const int rbase = m0 + m_warp + (lane >> 2);
    const int cbase = n0 + n_warp + (lane & 3) * 2;
    if (proj < 2) {
#pragma unroll
        for (int im = 0; im < MT; im++)
#pragma unroll
            for (int jn = 0; jn < NT; jn++) {
                const float* d = acc[im][jn];
                int r0 = rbase + im * 16;
                int c  = cbase + jn * 8;
                uint32_t h, l;
                split2(d[0], d[1], h, l);
                long b0a = (long)r0 * ldc + c;
                *reinterpret_cast<uint32_t*>(C_h + b0a) = h;
                *reinterpret_cast<uint32_t*>(C_l + b0a) = l;
                split2(d[2], d[3], h, l);
                long b1a = (long)(r0 + 8) * ldc + c;
                *reinterpret_cast<uint32_t*>(C_h + b1a) = h;
                *reinterpret_cast<uint32_t*>(C_l + b1a) = l;
            }
    } else {
        // ---- smem-transpose epilogue for V: [m][n] accums -> [n][m] smem ----
        __syncthreads();   // pipeline smem no longer needed
        constexpr int LDT = BM + 4;                     // 132 floats
        float* smt = reinterpret_cast<float*>(smem);    // [BN][LDT] = 67584 B
        const int lm = m_warp + (lane >> 2);            // local m base
        const int lc = n_warp + (lane & 3) * 2;         // local n base
#pragma unroll
        for (int im = 0; im < MT; im++)
#pragma unroll
            for (int jn = 0; jn < NT; jn++) {
                const float* d = acc[im][jn];
                int r0 = lm + im * 16;
                int c  = lc + jn * 8;
                smt[(c    ) * LDT + r0    ] = d[0];
                smt[(c + 1) * LDT + r0    ] = d[1];
                smt[(c    ) * LDT + r0 + 8] = d[2];
                smt[(c + 1) * LDT + r0 + 8] = d[3];
            }
        __syncthreads();
        // coalesced transposed store: half-warp per n-row (16 lanes x 16B)
        const int b2  = m0 >> 11;            // m0 / S_
        const int s2b = m0 & (S_ - 1);
#pragma unroll
        for (int itr = 0; itr < 8; itr++) {
            int task  = itr * 256 + tid;     // 0..2047
            int n_loc = task >> 4;           // 0..127
            int chunk = task & 15;           // 0..15 (8 floats each)
            int n_g = n0 + n_loc;
            int hidx = n_g >> 6, hd = n_g & 63;
            long rowb = (((long)b2 * H_ + hidx) * HD_ + hd) * S_ + s2b + chunk * 8;
            const float* src = &smt[n_loc * LDT + chunk * 8];
            uint32_t hw[4], lw[4];
#pragma unroll
            for (int p = 0; p < 4; p++)
                split2(src[2*p], src[2*p+1], hw[p], lw[p]);
            *reinterpret_cast<uint4*>(C_h + rowb) = make_uint4(hw[0], hw[1], hw[2], hw[3]);
            *reinterpret_cast<uint4*>(C_l + rowb) = make_uint4(lw[0], lw[1], lw[2], lw[3]);
        }
    }
}

// ---------------------------------------------------------------------------
// Generic batched GEMM, fp32 epilogue (*alpha). Scores + final GEMM.
// ---------------------------------------------------------------------------
__global__ __launch_bounds__(256, 2) void mma_gemm_f32(
    const __nv_bfloat16* __restrict__ Ah, const __nv_bfloat16* __restrict__ Al,
    const __nv_bfloat16* __restrict__ Bh, const __nv_bfloat16* __restrict__ Bl,
    float* __restrict__ C,
    int K, int lda, int ldb, int ldc,
    long offAb, long offAh_, long offBb, long offBh_, long offCb, long offCh_,
    int Hdiv, float alpha)
{
    GEMM_PREAMBLE
    const int z = blockIdx.z;
    const int bb = z / Hdiv, hh = z % Hdiv;
    const __nv_bfloat16* A_h = Ah + (long)bb * offAb + (long)hh * offAh_;
    const __nv_bfloat16* A_l = Al + (long)bb * offAb + (long)hh * offAh_;
    const __nv_bfloat16* B_h = Bh + (long)bb * offBb + (long)hh * offBh_;
    const __nv_bfloat16* B_l = Bl + (long)bb * offBb + (long)hh * offBh_;
    const long coff = (long)bb * offCb + (long)hh * offCh_;
    const int m0 = blockIdx.y * BM;
    const int n0 = blockIdx.x * BN;

    GEMM_MAINLOOP(A_h, A_l, B_h, B_l);

    const int rbase = m0 + m_warp + (lane >> 2);
    const int cbase = n0 + n_warp + (lane & 3) * 2;
#pragma unroll
    for (int im = 0; im < MT; im++)
#pragma unroll
        for (int jn = 0; jn < NT; jn++) {
            const float* d = acc[im][jn];
            int r0 = rbase + im * 16;
            int c  = cbase + jn * 8;
            *reinterpret_cast<float2*>(C + coff + (long)r0 * ldc + c) =
                make_float2(d[0] * alpha, d[1] * alpha);
            *reinterpret_cast<float2*>(C + coff + (long)(r0 + 8) * ldc + c) =
                make_float2(d[2] * alpha, d[3] * alpha);
        }
}

// ---------------------------------------------------------------------------
// AV GEMM: A fp32 (split on load), B bf16 pre-split. BM=128, BN=64, BK=32.
// ---------------------------------------------------------------------------
__global__ __launch_bounds__(256, 2) void mma_gemm_av(
    const float* __restrict__ Afp,
    const __nv_bfloat16* __restrict__ Bh, const __nv_bfloat16* __restrict__ Bl,
    __nv_bfloat16* __restrict__ Chi, __nv_bfloat16* __restrict__ Clo,
    int K, int lda, int ldb, int ldc,
    long offAb, long offAh_, long offBb, long offBh_, long offCb, long offCh_,
    int Hdiv)
{
    constexpr int BM = 128, BN = 64, BK = 32;
    constexpr int ROWB = 80;
    constexpr int ATILE = BM * ROWB;
    constexpr int BTILE = BN * ROWB;
    constexpr int STAGE = 2 * ATILE + 2 * BTILE;
    constexpr int AF4 = 2, BF4 = 1;
    constexpr int WARPS_M = 4, WARPS_N = 2;
    constexpr int MT = 2, NT = 4;

    extern __shared__ char smem[];
    const uint32_t sbase = smem_u32(smem);

    const int tid  = threadIdx.x;
    const int lane = tid & 31;
    const int wid  = tid >> 5;

    const int z = blockIdx.z;
    const int bb = z / Hdiv, hh = z % Hdiv;
    const float* A = Afp + (long)bb * offAb + (long)hh * offAh_;
    const __nv_bfloat16* B_h = Bh + (long)bb * offBb + (long)hh * offBh_;
    const __nv_bfloat16* B_l = Bl + (long)bb * offBb + (long)hh * offBh_;
    const long coff = (long)bb * offCb + (long)hh * offCh_;

    const int m0 = blockIdx.y * BM;
    const int n0 = blockIdx.x * BN;

    const int m_warp = (wid % WARPS_M) * (BM / WARPS_M);
    const int n_warp = (wid / WARPS_M) * (BN / WARPS_N);

    const uint32_t OFF_AH = 0, OFF_AL = ATILE, OFF_BH = 2*ATILE, OFF_BL = 2*ATILE + BTILE;

    float acc[MT][NT][4];
#pragma unroll
    for (int i = 0; i < MT; i++)
#pragma unroll
        for (int j = 0; j < NT; j++)
#pragma unroll
            for (int r = 0; r < 4; r++) acc[i][j][r] = 0.0f;

    uint4 rAh[AF4], rAl[AF4], rBh[BF4], rBl[BF4];

    auto gload = [&](int it) {
        const int kt = it * BK;
#pragma unroll
        for (int i = 0; i < AF4; i++) {
            int f4 = tid + i * 256;
            int row = f4 >> 2, c8 = f4 & 3;
            long g = (long)(m0 + row) * lda + kt + c8 * 8;
            float4 x0 = *reinterpret_cast<const float4*>(A + g);
            float4 x1 = *reinterpret_cast<const float4*>(A + g + 4);
            split8(x0, x1, rAh[i], rAl[i]);
        }
#pragma unroll
        for (int i = 0; i < BF4; i++) {
            int f4 = tid + i * 256;
            int row = f4 >> 2, c8 = f4 & 3;
            long g = (long)(n0 + row) * ldb + kt + c8 * 8;
            rBh[i] = *reinterpret_cast<const uint4*>(B_h + g);
            rBl[i] = *reinterpret_cast<const uint4*>(B_l + g);
        }
    };

    auto sstore = [&](int buf) {
        char* st = smem + buf * STAGE;
#pragma unroll
        for (int i = 0; i < AF4; i++) {
            int f4 = tid + i * 256;
            int row = f4 >> 2, c8 = f4 & 3;
            uint32_t o = row * ROWB + c8 * 16;
            *reinterpret_cast<uint4*>(st + OFF_AH + o) = rAh[i];
            *reinterpret_cast<uint4*>(st + OFF_AL + o) = rAl[i];
        }
#pragma unroll
        for (int i = 0; i < BF4; i++) {
            int f4 = tid + i * 256;
            int row = f4 >> 2, c8 = f4 & 3;
            uint32_t o = row * ROWB + c8 * 16;
            *reinterpret_cast<uint4*>(st + OFF_BH + o) = rBh[i];
            *reinterpret_cast<uint4*>(st + OFF_BL + o) = rBl[i];
        }
    };

    auto compute = [&](int buf) {
        const uint32_t st = sbase + buf * STAGE;
        const uint32_t a_row = m_warp + (lane & 15);
        const uint32_t a_k8  = (lane >> 4) * 16;
        const uint32_t b_row = n_warp + (lane & 7) + ((lane >> 4) & 1) * 8;
        const uint32_t b_k8  = ((lane >> 3) & 1) * 16;
#pragma unroll
        for (int ks = 0; ks < 2; ks++) {
            const uint32_t kbyte = ks * 32;
            uint32_t ah[MT][4], al[MT][4];
#pragma unroll
            for (int im = 0; im < MT; im++) {
                uint32_t addr = st + OFF_AH + (a_row + im * 16) * ROWB + kbyte + a_k8;
                ldmat_x4(ah[im][0], ah[im][1], ah[im][2], ah[im][3], addr);
                addr += ATILE;
                ldmat_x4(al[im][0], al[im][1], al[im][2], al[im][3], addr);
            }
            uint32_t bh[NT][2], bl[NT][2];
#pragma unroll
            for (int j2 = 0; j2 < NT / 2; j2++) {
                uint32_t addr = st + OFF_BH + (b_row + j2 * 16) * ROWB + kbyte + b_k8;
                ldmat_x4(bh[j2*2][0], bh[j2*2][1], bh[j2*2+1][0], bh[j2*2+1][1], addr);
                addr += BTILE;
                ldmat_x4(bl[j2*2][0], bl[j2*2][1], bl[j2*2+1][0], bl[j2*2+1][1], addr);
            }
#pragma unroll
            for (int im = 0; im < MT; im++)
#pragma unroll
                for (int jn = 0; jn < NT; jn++) {
                    float* d = acc[im][jn];
                    mma_bf16(d[0], d[1], d[2], d[3],
                             ah[im][0], ah[im][1], ah[im][2], ah[im][3],
                             bh[jn][0], bh[jn][1]);
                    mma_bf16(d[0], d[1], d[2], d[3],
                             ah[im][0], ah[im][1], ah[im][2], ah[im][3],
                             bl[jn][0], bl[jn][1]);
                    mma_bf16(d[0], d[1], d[2], d[3],
                             al[im][0], al[im][1], al[im][2], al[im][3],
                             bh[jn][0], bh[jn][1]);
                }
        }
    };

    const int NI = K / BK;
    gload(0);
    sstore(0);
    __syncthreads();
    int buf = 0;
    for (int it = 1; it < NI; it++) {
        gload(it);
        compute(buf);
        sstore(buf ^ 1);
        __syncthreads();
        buf ^= 1;
    }
    compute(buf);

    const int rbase = m0 + m_warp + (lane >> 2);
    const int cbase = n0 + n_warp + (lane & 3) * 2;
#pragma unroll
    for (int im = 0; im < MT; im++) {
#pragma unroll
        for (int jn = 0; jn < NT; jn++) {
            const float* d = acc[im][jn];
            int r0 = rbase + im * 16;
            int c  = cbase + jn * 8;
            uint32_t h, l;
            split2(d[0], d[1], h, l);
            long b0a = coff + (long)r0 * ldc + c;
            *reinterpret_cast<uint32_t*>(Chi + b0a) = h;
            *reinterpret_cast<uint32_t*>(Clo + b0a) = l;
            split2(d[2], d[3], h, l);
            long b1a = coff + (long)(r0 + 8) * ldc + c;
            *reinterpret_cast<uint32_t*>(Chi + b1a) = h;
            *reinterpret_cast<uint32_t*>(Clo + b1a) = l;
        }
    }
}

// ---------------------------------------------------------------------------
// Register-resident softmax: one read + one write per element.
// ---------------------------------------------------------------------------
__global__ __launch_bounds__(256) void softmax_rows2048(float* __restrict__ W)
{
    float4* p = reinterpret_cast<float4*>(W + (long)blockIdx.x * S_);
    const int t = threadIdx.x;
    const int lane = t & 31, warp = t >> 5;

    __shared__ float red[8];

    float4 x0 = p[t];
    float4 x1 = p[t + 256];

    float m = fmaxf(fmaxf(fmaxf(x0.x, x0.y), fmaxf(x0.z, x0.w)),
                    fmaxf(fmaxf(x1.x, x1.y), fmaxf(x1.z, x1.w)));
#pragma unroll
    for (int s = 16; s > 0; s >>= 1)
        m = fmaxf(m, __shfl_xor_sync(0xFFFFFFFFu, m, s));
    if (lane == 0) red[warp] = m;
    __syncthreads();
    {
        float v = red[lane & 7];
#pragma unroll
        for (int s = 4; s > 0; s >>= 1)
            v = fmaxf(v, __shfl_xor_sync(0xFFFFFFFFu, v, s));
        m = v;
    }

    x0.x = __expf(x0.x - m); x0.y = __expf(x0.y - m);
    x0.z = __expf(x0.z - m); x0.w = __expf(x0.w - m);
    x1.x = __expf(x1.x - m); x1.y = __expf(x1.y - m);
    x1.z = __expf(x1.z - m); x1.w = __expf(x1.w - m);
    float sum = (x0.x + x0.y) + (x0.z + x0.w) + (x1.x + x1.y) + (x1.z + x1.w);
#pragma unroll
    for (int s = 16; s > 0; s >>= 1)
        sum += __shfl_xor_sync(0xFFFFFFFFu, sum, s);
    __syncthreads();
    if (lane == 0) red[warp] = sum;
    __syncthreads();
    {
        float v = red[lane & 7];
#pragma unroll
        for (int s = 4; s > 0; s >>= 1)
            v += __shfl_xor_sync(0xFFFFFFFFu, v, s);
        sum = v;
    }

    const float inv = 1.0f / sum;
    x0.x *= inv; x0.y *= inv; x0.z *= inv; x0.w *= inv;
    x1.x *= inv; x1.y *= inv; x1.z *= inv; x1.w *= inv;
    p[t] = x0;
    p[t + 256] = x1;
}

// ---------------------------------------------------------------------------
extern "C" void kernel_launch(void* const* d_in, const int* in_sizes, int n_in,
                              void* d_out, int out_size)
{
    const float* Q  = (const float*)d_in[0];
    const float* K  = (const float*)d_in[1];
    const float* V  = (const float*)d_in[2];
    const float* Wq = (const float*)d_in[3];
    const float* Wk = (const float*)d_in[4];
    const float* Wv = (const float*)d_in[5];
    const float* Wo = (const float*)d_in[6];

    float* out = (float*)d_out;
    float* final_out = out;                       // [B,S,D]
    float* weights   = out + (long)B_ * S_ * D_;  // [B,H,S,S]

    __nv_bfloat16 *iQh,*iQl,*iKh,*iKl,*iVh,*iVl;
    __nv_bfloat16 *wqh,*wql,*wkh,*wkl,*wvh,*wvl,*woh,*wol;
    __nv_bfloat16 *qh,*ql,*kh,*kl,*vth,*vtl,*cath,*catl;
    cudaGetSymbolAddress((void**)&iQh, g_iQh); cudaGetSymbolAddress((void**)&iQl, g_iQl);
    cudaGetSymbolAddress((void**)&iKh, g_iKh); cudaGetSymbolAddress((void**)&iKl, g_iKl);
    cudaGetSymbolAddress((void**)&iVh, g_iVh); cudaGetSymbolAddress((void**)&iVl, g_iVl);
    cudaGetSymbolAddress((void**)&wqh, g_wqh); cudaGetSymbolAddress((void**)&wql, g_wql);
    cudaGetSymbolAddress((void**)&wkh, g_wkh); cudaGetSymbolAddress((void**)&wkl, g_wkl);
    cudaGetSymbolAddress((void**)&wvh, g_wvh); cudaGetSymbolAddress((void**)&wvl, g_wvl);
    cudaGetSymbolAddress((void**)&woh, g_woh); cudaGetSymbolAddress((void**)&wol, g_wol);
    cudaGetSymbolAddress((void**)&qh,  g_qh);  cudaGetSymbolAddress((void**)&ql,  g_ql);
    cudaGetSymbolAddress((void**)&kh,  g_kh);  cudaGetSymbolAddress((void**)&kl,  g_kl);
    cudaGetSymbolAddress((void**)&vth, g_vth); cudaGetSymbolAddress((void**)&vtl, g_vtl);
    cudaGetSymbolAddress((void**)&cath,g_cath);cudaGetSymbolAddress((void**)&catl,g_catl);

    constexpr int ROWB = 80;
    constexpr int SM_G  = 2 * (2 * 128 * ROWB + 2 * 128 * ROWB);  // 81920
    constexpr int SM_AV = 2 * (2 * 128 * ROWB + 2 * 64 * ROWB);   // 61440

    cudaFuncSetAttribute(mma_gemm_qkv, cudaFuncAttributeMaxDynamicSharedMemorySize, SM_G);
    cudaFuncSetAttribute(mma_gemm_f32, cudaFuncAttributeMaxDynamicSharedMemorySize, SM_G);
    cudaFuncSetAttribute(mma_gemm_av,  cudaFuncAttributeMaxDynamicSharedMemorySize, SM_AV);

    // 0) split all fp32 inputs into bf16 hi/lo (single launch)
    {
        dim3 g(BS_*D_/1024, 7, 1);
        split_all<<<g, 256>>>(Q, K, V, Wq, Wk, Wv, Wo,
                              iQh, iKh, iVh, wqh, wkh, wvh, woh,
                              iQl, iKl, iVl, wql, wkl, wvl, wol);
    }

    // 1) merged projections: q, k (split-bf16), v (transposed, coalesced)
    {
        dim3 g(D_/128, BS_/128, 3);
        mma_gemm_qkv<<<g, 256, SM_G>>>(iQh, iQl, iKh, iKl, iVh, iVl,
                                       wqh, wql, wkh, wkl, wvh, wvl,
                                       qh, ql, kh, kl, vth, vtl);
    }

    // 2) scores = 0.125 * q @ k^T -> weights (fp32, pre-softmax)
    {
        dim3 g(S_/128, S_/128, B_*H_);
        mma_gemm_f32<<<g, 256, SM_G>>>(qh, ql, kh, kl, weights,
            HD_, D_, D_, S_,
            (long)S_*D_, (long)HD_, (long)S_*D_, (long)HD_,
            (long)H_*S_*S_, (long)S_*S_, H_, 0.125f);
    }

    // 3) softmax in place
    softmax_rows2048<<<B_*H_*S_, 256>>>(weights);

    // 4) cat = softmax(scores) @ v
    {
        dim3 g(1, S_/128, B_*H_);
        mma_gemm_av<<<g, 256, SM_AV>>>(weights, vth, vtl,
            cath, catl,
            S_, S_, S_, D_,
            (long)H_*S_*S_, (long)S_*S_,
            (long)H_*HD_*S_, (long)HD_*S_,
            (long)S_*D_, (long)HD_, H_);
    }

    // 5) final = cat @ Wo^T (fp32 out)
    {
        dim3 g(D_/128, BS_/128, 1);
        mma_gemm_f32<<<g, 256, SM_G>>>(cath, catl, woh, wol, final_out,
            D_, D_, D_, D_, 0,0,0,0,0,0, 1, 1.0f);
    }
}

// round 14
// speedup vs baseline: 1.2162x; 1.1905x over previous
#include <cuda_runtime.h>
#include <cuda_bf16.h>
#include <cuda_fp16.h>
#include <stdint.h>
#include <math.h>

#define B_ 2
#define S_ 2048
#define D_ 1024
#define H_ 16
#define HD_ 64
#define BS_ (B_*S_)

// ---------------- 16-bit split scratch (raw storage; format = fp16 hi/lo) ---
__device__ __nv_bfloat16 g_iQh[BS_*D_], g_iQl[BS_*D_];
__device__ __nv_bfloat16 g_iKh[BS_*D_], g_iKl[BS_*D_];
__device__ __nv_bfloat16 g_iVh[BS_*D_], g_iVl[BS_*D_];
__device__ __nv_bfloat16 g_wqh[D_*D_], g_wql[D_*D_];
__device__ __nv_bfloat16 g_wkh[D_*D_], g_wkl[D_*D_];
__device__ __nv_bfloat16 g_wvh[D_*D_], g_wvl[D_*D_];
__device__ __nv_bfloat16 g_woh[D_*D_], g_wol[D_*D_];
__device__ __nv_bfloat16 g_qh[BS_*D_], g_ql[BS_*D_];
__device__ __nv_bfloat16 g_kh[BS_*D_], g_kl[BS_*D_];
__device__ __nv_bfloat16 g_vth[BS_*D_], g_vtl[BS_*D_];   // [B,H,HD,S]
__device__ __nv_bfloat16 g_cath[BS_*D_], g_catl[BS_*D_]; // [B,S,D]

// ---------------- helpers ----------------
__device__ __forceinline__ uint32_t smem_u32(const void* p){
    uint32_t a;
    asm("{ .reg .u64 t; cvta.to.shared.u64 t, %1; cvt.u32.u64 %0, t; }" : "=r"(a) : "l"(p));
    return a;
}
__device__ __forceinline__ void cp_async16(uint32_t saddr, const void* g){
    asm volatile("cp.async.cg.shared.global [%0], [%1], 16;" :: "r"(saddr), "l"(g));
}
#define CP_COMMIT() asm volatile("cp.async.commit_group;" ::: "memory")
#define CP_WAIT1()  asm volatile("cp.async.wait_group 1;"  ::: "memory")

__device__ __forceinline__ void ldmat_x4(uint32_t& r0, uint32_t& r1, uint32_t& r2,
                                         uint32_t& r3, uint32_t addr){
    asm volatile("ldmatrix.sync.aligned.m8n8.x4.shared.b16 {%0,%1,%2,%3}, [%4];"
        : "=r"(r0), "=r"(r1), "=r"(r2), "=r"(r3) : "r"(addr));
}
// fp16 MMA, fp32 accumulate
__device__ __forceinline__ void mma_f16(float& d0, float& d1, float& d2, float& d3,
                                        uint32_t a0, uint32_t a1, uint32_t a2, uint32_t a3,
                                        uint32_t b0, uint32_t b1){
    asm volatile("mma.sync.aligned.m16n8k16.row.col.f32.f16.f16.f32 "
        "{%0,%1,%2,%3}, {%4,%5,%6,%7}, {%8,%9}, {%0,%1,%2,%3};"
        : "+f"(d0), "+f"(d1), "+f"(d2), "+f"(d3)
        : "r"(a0), "r"(a1), "r"(a2), "r"(a3), "r"(b0), "r"(b1));
}
// fp16 hi/lo split of two floats, packed as 2x16-bit
__device__ __forceinline__ void split2(float a, float b, uint32_t& h, uint32_t& l){
    __half ha = __float2half_rn(a), hb = __float2half_rn(b);
    h = ((uint32_t)__half_as_ushort(ha)) | (((uint32_t)__half_as_ushort(hb)) << 16);
    __half la = __float2half_rn(a - __half2float(ha));
    __half lb = __float2half_rn(b - __half2float(hb));
    l = ((uint32_t)__half_as_ushort(la)) | (((uint32_t)__half_as_ushort(lb)) << 16);
}
__device__ __forceinline__ void split8(const float4& x0, const float4& x1,
                                       uint4& h, uint4& l){
    split2(x0.x, x0.y, h.x, l.x);
    split2(x0.z, x0.w, h.y, l.y);
    split2(x1.x, x1.y, h.z, l.z);
    split2(x1.z, x1.w, h.w, l.w);
}

// ---------------- one-shot split of all 7 fp32 tensors ----------------
__global__ __launch_bounds__(256) void split_all(
    const float* __restrict__ i0, const float* __restrict__ i1,
    const float* __restrict__ i2, const float* __restrict__ i3,
    const float* __restrict__ i4, const float* __restrict__ i5,
    const float* __restrict__ i6,
    __nv_bfloat16* __restrict__ h0, __nv_bfloat16* __restrict__ h1,
    __nv_bfloat16* __restrict__ h2, __nv_bfloat16* __restrict__ h3,
    __nv_bfloat16* __restrict__ h4, __nv_bfloat16* __restrict__ h5,
    __nv_bfloat16* __restrict__ h6,
    __nv_bfloat16* __restrict__ l0, __nv_bfloat16* __restrict__ l1,
    __nv_bfloat16* __restrict__ l2, __nv_bfloat16* __restrict__ l3,
    __nv_bfloat16* __restrict__ l4, __nv_bfloat16* __restrict__ l5,
    __nv_bfloat16* __restrict__ l6)
{
    const int t = blockIdx.y;
    const int n = (t < 3) ? BS_*D_ : D_*D_;
    int i = (blockIdx.x * 256 + threadIdx.x) * 4;
    if (i >= n) return;
    const float* in = (t==0)?i0:(t==1)?i1:(t==2)?i2:(t==3)?i3:(t==4)?i4:(t==5)?i5:i6;
    __nv_bfloat16* hi = (t==0)?h0:(t==1)?h1:(t==2)?h2:(t==3)?h3:(t==4)?h4:(t==5)?h5:h6;
    __nv_bfloat16* lo = (t==0)?l0:(t==1)?l1:(t==2)?l2:(t==3)?l3:(t==4)?l4:(t==5)?l5:l6;
    float4 x = *reinterpret_cast<const float4*>(in + i);
    uint32_t a0, b0, a1, b1;
    split2(x.x, x.y, a0, b0);
    split2(x.z, x.w, a1, b1);
    *reinterpret_cast<uint2*>(hi + i) = make_uint2(a0, a1);
    *reinterpret_cast<uint2*>(lo + i) = make_uint2(b0, b1);
}

// ===========================================================================
// Shared GEMM machinery: BM=128, BN=128, BK=32, 8 warps, 2-stage cp.async,
// occupancy 2, 80B padded rows. fp16 2-pass: A split hi/lo, B hi only.
// ===========================================================================
#define GEMM_CONSTS \
    constexpr int BM = 128, BN = 128, BK = 32; \
    constexpr int ROWB = 80; \
    constexpr int ATILE = BM * ROWB; \
    constexpr int BTILE = BN * ROWB; \
    constexpr int STAGE = 2 * ATILE + BTILE; \
    constexpr int WARPS_M = 2, WARPS_N = 4; \
    constexpr int MT = 4, NT = 4; \
    (void)sizeof(char[WARPS_M + WARPS_N]);

#define GEMM_ISSUE(st, Ah_p, Al_p, Bh_p, kt) do { \
    _Pragma("unroll") \
    for (int i_ = 0; i_ < 2; i_++) { \
        int row_ = l_row + i_ * 64; \
        long g_ = (long)(m0 + row_) * lda + (kt) + l_c8 * 8; \
        uint32_t o_ = so + i_ * 64 * ROWB; \
        cp_async16((st) + 0     + o_, (Ah_p) + g_); \
        cp_async16((st) + ATILE + o_, (Al_p) + g_); \
    } \
    _Pragma("unroll") \
    for (int i_ = 0; i_ < 2; i_++) { \
        int row_ = l_row + i_ * 64; \
        long g_ = (long)(n0 + row_) * ldb + (kt) + l_c8 * 8; \
        uint32_t o_ = so + i_ * 64 * ROWB; \
        cp_async16((st) + 2*ATILE + o_, (Bh_p) + g_); \
    } \
} while(0)

#define GEMM_COMPUTE(st) do { \
    const uint32_t a_row_ = m_warp + (lane & 15); \
    const uint32_t a_k8_  = (lane >> 4) * 16; \
    const uint32_t b_row_ = n_warp + (lane & 7) + ((lane >> 4) & 1) * 8; \
    const uint32_t b_k8_  = ((lane >> 3) & 1) * 16; \
    _Pragma("unroll") \
    for (int ks_ = 0; ks_ < 2; ks_++) { \
        const uint32_t kb_ = ks_ * 32; \
        uint32_t ah_[MT][4], al_[MT][4]; \
        _Pragma("unroll") \
        for (int im_ = 0; im_ < MT; im_++) { \
            uint32_t ad_ = (st) + (a_row_ + im_ * 16) * ROWB + kb_ + a_k8_; \
            ldmat_x4(ah_[im_][0], ah_[im_][1], ah_[im_][2], ah_[im_][3], ad_); \
            ad_ += ATILE; \
            ldmat_x4(al_[im_][0], al_[im_][1], al_[im_][2], al_[im_][3], ad_); \
        } \
        uint32_t bh_[NT][2]; \
        _Pragma("unroll") \
        for (int j2_ = 0; j2_ < NT/2; j2_++) { \
            uint32_t ad_ = (st) + 2*ATILE + (b_row_ + j2_ * 16) * ROWB + kb_ + b_k8_; \
            ldmat_x4(bh_[j2_*2][0], bh_[j2_*2][1], bh_[j2_*2+1][0], bh_[j2_*2+1][1], ad_); \
        } \
        _Pragma("unroll") \
        for (int im_ = 0; im_ < MT; im_++) \
        _Pragma("unroll") \
        for (int jn_ = 0; jn_ < NT; jn_++) { \
            float* d_ = acc[im_][jn_]; \
            mma_f16(d_[0], d_[1], d_[2], d_[3], \
                    ah_[im_][0], ah_[im_][1], ah_[im_][2], ah_[im_][3], \
                    bh_[jn_][0], bh_[jn_][1]); \
            mma_f16(d_[0], d_[1], d_[2], d_[3], \
                    al_[im_][0], al_[im_][1], al_[im_][2], al_[im_][3], \
                    bh_[jn_][0], bh_[jn_][1]); \
        } \
    } \
} while(0)

#define GEMM_MAINLOOP(Ah_p, Al_p, Bh_p) do { \
    const int NI_ = K / BK; \
    GEMM_ISSUE(sbase, Ah_p, Al_p, Bh_p, 0); \
    CP_COMMIT(); \
    if (NI_ > 1) GEMM_ISSUE(sbase + STAGE, Ah_p, Al_p, Bh_p, BK); \
    CP_COMMIT(); \
    for (int it_ = 0; it_ < NI_; it_++) { \
        CP_WAIT1(); \
        __syncthreads(); \
        GEMM_COMPUTE(sbase + (it_ & 1) * STAGE); \
        __syncthreads(); \
        if (it_ + 2 < NI_) \
            GEMM_ISSUE(sbase + (it_ & 1) * STAGE, Ah_p, Al_p, Bh_p, (it_ + 2) * BK); \
        CP_COMMIT(); \
    } \
} while(0)

#define GEMM_PREAMBLE \
    GEMM_CONSTS \
    extern __shared__ char smem[]; \
    const uint32_t sbase = smem_u32(smem); \
    const int tid  = threadIdx.x; \
    const int lane = tid & 31; \
    const int wid  = tid >> 5; \
    const int m_warp = (wid % WARPS_M) * (BM / WARPS_M); \
    const int n_warp = (wid / WARPS_M) * (BN / WARPS_N); \
    const int l_row = tid >> 2; \
    const int l_c8  = tid & 3; \
    const uint32_t so = l_row * ROWB + l_c8 * 16; \
    float acc[MT][NT][4]; \
    _Pragma("unroll") \
    for (int i_ = 0; i_ < MT; i_++) \
    _Pragma("unroll") \
    for (int j_ = 0; j_ < NT; j_++) \
    _Pragma("unroll") \
    for (int r_ = 0; r_ < 4; r_++) acc[i_][j_][r_] = 0.0f;

// ---------------------------------------------------------------------------
// Merged Q/K/V projection GEMM. proj 0,1: split store. proj 2: transposed.
// ---------------------------------------------------------------------------
__global__ __launch_bounds__(256, 2) void mma_gemm_qkv(
    const __nv_bfloat16* __restrict__ iQh, const __nv_bfloat16* __restrict__ iQl,
    const __nv_bfloat16* __restrict__ iKh, const __nv_bfloat16* __restrict__ iKl,
    const __nv_bfloat16* __restrict__ iVh, const __nv_bfloat16* __restrict__ iVl,
    const __nv_bfloat16* __restrict__ wqh,
    const __nv_bfloat16* __restrict__ wkh,
    const __nv_bfloat16* __restrict__ wvh,
    __nv_bfloat16* __restrict__ qh, __nv_bfloat16* __restrict__ ql,
    __nv_bfloat16* __restrict__ kh, __nv_bfloat16* __restrict__ kl,
    __nv_bfloat16* __restrict__ vth, __nv_bfloat16* __restrict__ vtl)
{
    GEMM_PREAMBLE
    const int K = D_, lda = D_, ldb = D_, ldc = D_;
    const int m0 = blockIdx.y * BM;
    const int n0 = blockIdx.x * BN;
    const int proj = blockIdx.z;

    const __nv_bfloat16* A_h = (proj==0) ? iQh : (proj==1) ? iKh : iVh;
    const __nv_bfloat16* A_l = (proj==0) ? iQl : (proj==1) ? iKl : iVl;
    const __nv_bfloat16* B_h = (proj==0) ? wqh : (proj==1) ? wkh : wvh;
    __nv_bfloat16* C_h = (proj==0) ? qh : (proj==1) ? kh : vth;
    __nv_bfloat16* C_l = (proj==0) ? ql : (proj==1) ? kl : vtl;

    GEMM_MAINLOOP(A_h, A_l, B_h);

    const int rbase = m0 + m_warp + (lane >> 2);
    const int cbase = n0 + n_warp + (lane & 3) * 2;
    if (proj < 2) {
#pragma unroll
        for (int im = 0; im < MT; im++)
#pragma unroll
            for (int jn = 0; jn < NT; jn++) {
                const float* d = acc[im][jn];
                int r0 = rbase + im * 16;
                int c  = cbase + jn * 8;
                uint32_t h, l;
                split2(d[0], d[1], h, l);
                long b0a = (long)r0 * ldc + c;
                *reinterpret_cast<uint32_t*>(C_h + b0a) = h;
                *reinterpret_cast<uint32_t*>(C_l + b0a) = l;
                split2(d[2], d[3], h, l);
                long b1a = (long)(r0 + 8) * ldc + c;
                *reinterpret_cast<uint32_t*>(C_h + b1a) = h;
                *reinterpret_cast<uint32_t*>(C_l + b1a) = l;
            }
    } else {
#pragma unroll
        for (int im = 0; im < MT; im++)
#pragma unroll
            for (int jn = 0; jn < NT; jn++) {
                const float* d = acc[im][jn];
                int r0 = rbase + im * 16;
                int c  = cbase + jn * 8;
#pragma unroll
                for (int e = 0; e < 4; e++) {
                    int m = r0 + (e >> 1) * 8;
                    int n = c + (e & 1);
                    float f = d[e];
                    __half hv = __float2half_rn(f);
                    __half lv = __float2half_rn(f - __half2float(hv));
                    int b2 = m >> 11, s2 = m & (S_ - 1);
                    int hidx = n >> 6, hd = n & 63;
                    long addr = (((long)b2 * H_ + hidx) * HD_ + hd) * S_ + s2;
                    *reinterpret_cast<unsigned short*>(C_h + addr) = __half_as_ushort(hv);
                    *reinterpret_cast<unsigned short*>(C_l + addr) = __half_as_ushort(lv);
                }
            }
    }
}

// ---------------------------------------------------------------------------
// Generic batched GEMM, fp32 epilogue (*alpha). Scores + final GEMM.
// ---------------------------------------------------------------------------
__global__ __launch_bounds__(256, 2) void mma_gemm_f32(
    const __nv_bfloat16* __restrict__ Ah, const __nv_bfloat16* __restrict__ Al,
    const __nv_bfloat16* __restrict__ Bh,
    float* __restrict__ C,
    int K, int lda, int ldb, int ldc,
    long offAb, long offAh_, long offBb, long offBh_, long offCb, long offCh_,
    int Hdiv, float alpha)
{
    GEMM_PREAMBLE
    const int z = blockIdx.z;
    const int bb = z / Hdiv, hh = z % Hdiv;
    const __nv_bfloat16* A_h = Ah + (long)bb * offAb + (long)hh * offAh_;
    const __nv_bfloat16* A_l = Al + (long)bb * offAb + (long)hh * offAh_;
    const __nv_bfloat16* B_h = Bh + (long)bb * offBb + (long)hh * offBh_;
    const long coff = (long)bb * offCb + (long)hh * offCh_;
    const int m0 = blockIdx.y * BM;
    const int n0 = blockIdx.x * BN;

    GEMM_MAINLOOP(A_h, A_l, B_h);

    const int rbase = m0 + m_warp + (lane >> 2);
    const int cbase = n0 + n_warp + (lane & 3) * 2;
#pragma unroll
    for (int im = 0; im < MT; im++)
#pragma unroll
        for (int jn = 0; jn < NT; jn++) {
            const float* d = acc[im][jn];
            int r0 = rbase + im * 16;
            int c  = cbase + jn * 8;
            *reinterpret_cast<float2*>(C + coff + (long)r0 * ldc + c) =
                make_float2(d[0] * alpha, d[1] * alpha);
            *reinterpret_cast<float2*>(C + coff + (long)(r0 + 8) * ldc + c) =
                make_float2(d[2] * alpha, d[3] * alpha);
        }
}

// ---------------------------------------------------------------------------
// AV GEMM: A fp32 (fp16-split on load), B fp16-hi. BM=128, BN=64, BK=32.
// ---------------------------------------------------------------------------
__global__ __launch_bounds__(256, 2) void mma_gemm_av(
    const float* __restrict__ Afp,
    const __nv_bfloat16* __restrict__ Bh,
    __nv_bfloat16* __restrict__ Chi, __nv_bfloat16* __restrict__ Clo,
    int K, int lda, int ldb, int ldc,
    long offAb, long offAh_, long offBb, long offBh_, long offCb, long offCh_,
    int Hdiv)
{
    constexpr int BM = 128, BN = 64, BK = 32;
    constexpr int ROWB = 80;
    constexpr int ATILE = BM * ROWB;
    constexpr int BTILE = BN * ROWB;
    constexpr int STAGE = 2 * ATILE + BTILE;
    constexpr int AF4 = 2, BF4 = 1;
    constexpr int WARPS_M = 4, WARPS_N = 2;
    constexpr int MT = 2, NT = 4;

    extern __shared__ char smem[];
    const uint32_t sbase = smem_u32(smem);

    const int tid  = threadIdx.x;
    const int lane = tid & 31;
    const int wid  = tid >> 5;

    const int z = blockIdx.z;
    const int bb = z / Hdiv, hh = z % Hdiv;
    const float* A = Afp + (long)bb * offAb + (long)hh * offAh_;
    const __nv_bfloat16* B_h = Bh + (long)bb * offBb + (long)hh * offBh_;
    const long coff = (long)bb * offCb + (long)hh * offCh_;

    const int m0 = blockIdx.y * BM;
    const int n0 = blockIdx.x * BN;

    const int m_warp = (wid % WARPS_M) * (BM / WARPS_M);
    const int n_warp = (wid / WARPS_M) * (BN / WARPS_N);

    const uint32_t OFF_AH = 0, OFF_AL = ATILE, OFF_BH = 2*ATILE;

    float acc[MT][NT][4];
#pragma unroll
    for (int i = 0; i < MT; i++)
#pragma unroll
        for (int j = 0; j < NT; j++)
#pragma unroll
            for (int r = 0; r < 4; r++) acc[i][j][r] = 0.0f;

    uint4 rAh[AF4], rAl[AF4], rBh[BF4];

    auto gload = [&](int it) {
        const int kt = it * BK;
#pragma unroll
        for (int i = 0; i < AF4; i++) {
            int f4 = tid + i * 256;
            int row = f4 >> 2, c8 = f4 & 3;
            long g = (long)(m0 + row) * lda + kt + c8 * 8;
            float4 x0 = *reinterpret_cast<const float4*>(A + g);
            float4 x1 = *reinterpret_cast<const float4*>(A + g + 4);
            split8(x0, x1, rAh[i], rAl[i]);
        }
#pragma unroll
        for (int i = 0; i < BF4; i++) {
            int f4 = tid + i * 256;
            int row = f4 >> 2, c8 = f4 & 3;
            long g = (long)(n0 + row) * ldb + kt + c8 * 8;
            rBh[i] = *reinterpret_cast<const uint4*>(B_h + g);
        }
    };

    auto sstore = [&](int buf) {
        char* st = smem + buf * STAGE;
#pragma unroll
        for (int i = 0; i < AF4; i++) {
            int f4 = tid + i * 256;
            int row = f4 >> 2, c8 = f4 & 3;
            uint32_t o = row * ROWB + c8 * 16;
            *reinterpret_cast<uint4*>(st + OFF_AH + o) = rAh[i];
            *reinterpret_cast<uint4*>(st + OFF_AL + o) = rAl[i];
        }
#pragma unroll
        for (int i = 0; i < BF4; i++) {
            int f4 = tid + i * 256;
            int row = f4 >> 2, c8 = f4 & 3;
            uint32_t o = row * ROWB + c8 * 16;
            *reinterpret_cast<uint4*>(st + OFF_BH + o) = rBh[i];
        }
    };

    auto compute = [&](int buf) {
        const uint32_t st = sbase + buf * STAGE;
        const uint32_t a_row = m_warp + (lane & 15);
        const uint32_t a_k8  = (lane >> 4) * 16;
        const uint32_t b_row = n_warp + (lane & 7) + ((lane >> 4) & 1) * 8;
        const uint32_t b_k8  = ((lane >> 3) & 1) * 16;
#pragma unroll
        for (int ks = 0; ks < 2; ks++) {
            const uint32_t kbyte = ks * 32;
            uint32_t ah[MT][4], al[MT][4];
#pragma unroll
            for (int im = 0; im < MT; im++) {
                uint32_t addr = st + OFF_AH + (a_row + im * 16) * ROWB + kbyte + a_k8;
                ldmat_x4(ah[im][0], ah[im][1], ah[im][2], ah[im][3], addr);
                addr += ATILE;
                ldmat_x4(al[im][0], al[im][1], al[im][2], al[im][3], addr);
            }
            uint32_t bh[NT][2];
#pragma unroll
            for (int j2 = 0; j2 < NT / 2; j2++) {
                uint32_t addr = st + OFF_BH + (b_row + j2 * 16) * ROWB + kbyte + b_k8;
                ldmat_x4(bh[j2*2][0], bh[j2*2][1], bh[j2*2+1][0], bh[j2*2+1][1], addr);
            }
#pragma unroll
            for (int im = 0; im < MT; im++)
#pragma unroll
                for (int jn = 0; jn < NT; jn++) {
                    float* d = acc[im][jn];
                    mma_f16(d[0], d[1], d[2], d[3],
                            ah[im][0], ah[im][1], ah[im][2], ah[im][3],
                            bh[jn][0], bh[jn][1]);
                    mma_f16(d[0], d[1], d[2], d[3],
                            al[im][0], al[im][1], al[im][2], al[im][3],
                            bh[jn][0], bh[jn][1]);
                }
        }
    };

    const int NI = K / BK;
    gload(0);
    sstore(0);
    __syncthreads();
    int buf = 0;
    for (int it = 1; it < NI; it++) {
        gload(it);
        compute(buf);
        sstore(buf ^ 1);
        __syncthreads();
        buf ^= 1;
    }
    compute(buf);

    const int rbase = m0 + m_warp + (lane >> 2);
    const int cbase = n0 + n_warp + (lane & 3) * 2;
#pragma unroll
    for (int im = 0; im < MT; im++) {
#pragma unroll
        for (int jn = 0; jn < NT; jn++) {
            const float* d = acc[im][jn];
            int r0 = rbase + im * 16;
            int c  = cbase + jn * 8;
            uint32_t h, l;
            split2(d[0], d[1], h, l);
            long b0a = coff + (long)r0 * ldc + c;
            *reinterpret_cast<uint32_t*>(Chi + b0a) = h;
            *reinterpret_cast<uint32_t*>(Clo + b0a) = l;
            split2(d[2], d[3], h, l);
            long b1a = coff + (long)(r0 + 8) * ldc + c;
            *reinterpret_cast<uint32_t*>(Chi + b1a) = h;
            *reinterpret_cast<uint32_t*>(Clo + b1a) = l;
        }
    }
}

// ---------------------------------------------------------------------------
// Register-resident softmax: one read + one write per element.
// ---------------------------------------------------------------------------
__global__ __launch_bounds__(256) void softmax_rows2048(float* __restrict__ W)
{
    float4* p = reinterpret_cast<float4*>(W + (long)blockIdx.x * S_);
    const int t = threadIdx.x;
    const int lane = t & 31, warp = t >> 5;

    __shared__ float red[8];

    float4 x0 = p[t];
    float4 x1 = p[t + 256];

    float m = fmaxf(fmaxf(fmaxf(x0.x, x0.y), fmaxf(x0.z, x0.w)),
                    fmaxf(fmaxf(x1.x, x1.y), fmaxf(x1.z, x1.w)));
#pragma unroll
    for (int s = 16; s > 0; s >>= 1)
        m = fmaxf(m, __shfl_xor_sync(0xFFFFFFFFu, m, s));
    if (lane == 0) red[warp] = m;
    __syncthreads();
    {
        float v = red[lane & 7];
#pragma unroll
        for (int s = 4; s > 0; s >>= 1)
            v = fmaxf(v, __shfl_xor_sync(0xFFFFFFFFu, v, s));
        m = v;
    }

    x0.x = __expf(x0.x - m); x0.y = __expf(x0.y - m);
    x0.z = __expf(x0.z - m); x0.w = __expf(x0.w - m);
    x1.x = __expf(x1.x - m); x1.y = __expf(x1.y - m);
    x1.z = __expf(x1.z - m); x1.w = __expf(x1.w - m);
    float sum = (x0.x + x0.y) + (x0.z + x0.w) + (x1.x + x1.y) + (x1.z + x1.w);
#pragma unroll
    for (int s = 16; s > 0; s >>= 1)
        sum += __shfl_xor_sync(0xFFFFFFFFu, sum, s);
    __syncthreads();
    if (lane == 0) red[warp] = sum;
    __syncthreads();
    {
        float v = red[lane & 7];
#pragma unroll
        for (int s = 4; s > 0; s >>= 1)
            v += __shfl_xor_sync(0xFFFFFFFFu, v, s);
        sum = v;
    }

    const float inv = 1.0f / sum;
    x0.x *= inv; x0.y *= inv; x0.z *= inv; x0.w *= inv;
    x1.x *= inv; x1.y *= inv; x1.z *= inv; x1.w *= inv;
    p[t] = x0;
    p[t + 256] = x1;
}

// ---------------------------------------------------------------------------
extern "C" void kernel_launch(void* const* d_in, const int* in_sizes, int n_in,
                              void* d_out, int out_size)
{
    const float* Q  = (const float*)d_in[0];
    const float* K  = (const float*)d_in[1];
    const float* V  = (const float*)d_in[2];
    const float* Wq = (const float*)d_in[3];
    const float* Wk = (const float*)d_in[4];
    const float* Wv = (const float*)d_in[5];
    const float* Wo = (const float*)d_in[6];

    float* out = (float*)d_out;
    float* final_out = out;                       // [B,S,D]
    float* weights   = out + (long)B_ * S_ * D_;  // [B,H,S,S]

    __nv_bfloat16 *iQh,*iQl,*iKh,*iKl,*iVh,*iVl;
    __nv_bfloat16 *wqh,*wql,*wkh,*wkl,*wvh,*wvl,*woh,*wol;
    __nv_bfloat16 *qh,*ql,*kh,*kl,*vth,*vtl,*cath,*catl;
    cudaGetSymbolAddress((void**)&iQh, g_iQh); cudaGetSymbolAddress((void**)&iQl, g_iQl);
    cudaGetSymbolAddress((void**)&iKh, g_iKh); cudaGetSymbolAddress((void**)&iKl, g_iKl);
    cudaGetSymbolAddress((void**)&iVh, g_iVh); cudaGetSymbolAddress((void**)&iVl, g_iVl);
    cudaGetSymbolAddress((void**)&wqh, g_wqh); cudaGetSymbolAddress((void**)&wql, g_wql);
    cudaGetSymbolAddress((void**)&wkh, g_wkh); cudaGetSymbolAddress((void**)&wkl, g_wkl);
    cudaGetSymbolAddress((void**)&wvh, g_wvh); cudaGetSymbolAddress((void**)&wvl, g_wvl);
    cudaGetSymbolAddress((void**)&woh, g_woh); cudaGetSymbolAddress((void**)&wol, g_wol);
    cudaGetSymbolAddress((void**)&qh,  g_qh);  cudaGetSymbolAddress((void**)&ql,  g_ql);
    cudaGetSymbolAddress((void**)&kh,  g_kh);  cudaGetSymbolAddress((void**)&kl,  g_kl);
    cudaGetSymbolAddress((void**)&vth, g_vth); cudaGetSymbolAddress((void**)&vtl, g_vtl);
    cudaGetSymbolAddress((void**)&cath,g_cath);cudaGetSymbolAddress((void**)&catl,g_catl);

    constexpr int ROWB = 80;
    constexpr int SM_G  = 2 * (2 * 128 * ROWB + 128 * ROWB);  // 61440
    constexpr int SM_AV = 2 * (2 * 128 * ROWB + 64 * ROWB);   // 51200

    cudaFuncSetAttribute(mma_gemm_qkv, cudaFuncAttributeMaxDynamicSharedMemorySize, SM_G);
    cudaFuncSetAttribute(mma_gemm_f32, cudaFuncAttributeMaxDynamicSharedMemorySize, SM_G);
    cudaFuncSetAttribute(mma_gemm_av,  cudaFuncAttributeMaxDynamicSharedMemorySize, SM_AV);

    // 0) split all fp32 inputs into fp16 hi/lo (single launch)
    {
        dim3 g(BS_*D_/1024, 7, 1);
        split_all<<<g, 256>>>(Q, K, V, Wq, Wk, Wv, Wo,
                              iQh, iKh, iVh, wqh, wkh, wvh, woh,
                              iQl, iKl, iVl, wql, wkl, wvl, wol);
    }

    // 1) merged projections (B = weight hi only)
    {
        dim3 g(D_/128, BS_/128, 3);
        mma_gemm_qkv<<<g, 256, SM_G>>>(iQh, iQl, iKh, iKl, iVh, iVl,
                                       wqh, wkh, wvh,
                                       qh, ql, kh, kl, vth, vtl);
    }

    // 2) scores = 0.125 * q @ k^T -> weights (fp32, pre-softmax)
    {
        dim3 g(S_/128, S_/128, B_*H_);
        mma_gemm_f32<<<g, 256, SM_G>>>(qh, ql, kh, weights,
            HD_, D_, D_, S_,
            (long)S_*D_, (long)HD_, (long)S_*D_, (long)HD_,
            (long)H_*S_*S_, (long)S_*S_, H_, 0.125f);
    }

    // 3) softmax in place
    softmax_rows2048<<<B_*H_*S_, 256>>>(weights);

    // 4) cat = softmax(scores) @ v
    {
        dim3 g(1, S_/128, B_*H_);
        mma_gemm_av<<<g, 256, SM_AV>>>(weights, vth,
            cath, catl,
            S_, S_, S_, D_,
            (long)H_*S_*S_, (long)S_*S_,
            (long)H_*HD_*S_, (long)HD_*S_,
            (long)S_*D_, (long)HD_, H_);
    }

    // 5) final = cat @ Wo^T (fp32 out)
    {
        dim3 g(D_/128, BS_/128, 1);
        mma_gemm_f32<<<g, 256, SM_G>>>(cath, catl, woh, final_out,
            D_, D_, D_, D_, 0,0,0,0,0,0, 1, 1.0f);
    }
}

// round 15
// speedup vs baseline: 1.2516x; 1.0291x over previous
#include <cuda_runtime.h>
#include <cuda_bf16.h>
#include <cuda_fp16.h>
#include <stdint.h>
#include <math.h>

#define B_ 2
#define S_ 2048
#define D_ 1024
#define H_ 16
#define HD_ 64
#define BS_ (B_*S_)

// ---------------- 16-bit split scratch (raw storage; format = fp16 hi/lo) ---
__device__ __nv_bfloat16 g_iQh[BS_*D_], g_iQl[BS_*D_];
__device__ __nv_bfloat16 g_iKh[BS_*D_], g_iKl[BS_*D_];
__device__ __nv_bfloat16 g_iVh[BS_*D_], g_iVl[BS_*D_];
__device__ __nv_bfloat16 g_wqh[D_*D_], g_wql[D_*D_];
__device__ __nv_bfloat16 g_wkh[D_*D_], g_wkl[D_*D_];
__device__ __nv_bfloat16 g_wvh[D_*D_], g_wvl[D_*D_];
__device__ __nv_bfloat16 g_woh[D_*D_], g_wol[D_*D_];
__device__ __nv_bfloat16 g_qh[BS_*D_], g_ql[BS_*D_];
__device__ __nv_bfloat16 g_kh[BS_*D_], g_kl[BS_*D_];
__device__ __nv_bfloat16 g_vth[BS_*D_], g_vtl[BS_*D_];   // [B,H,HD,S]
__device__ __nv_bfloat16 g_cath[BS_*D_], g_catl[BS_*D_]; // [B,S,D]

// ---------------- helpers ----------------
__device__ __forceinline__ uint32_t smem_u32(const void* p){
    uint32_t a;
    asm("{ .reg .u64 t; cvta.to.shared.u64 t, %1; cvt.u32.u64 %0, t; }" : "=r"(a) : "l"(p));
    return a;
}
__device__ __forceinline__ void cp_async16(uint32_t saddr, const void* g){
    asm volatile("cp.async.cg.shared.global [%0], [%1], 16;" :: "r"(saddr), "l"(g));
}
#define CP_COMMIT() asm volatile("cp.async.commit_group;" ::: "memory")
#define CP_WAIT1()  asm volatile("cp.async.wait_group 1;"  ::: "memory")

__device__ __forceinline__ void ldmat_x4(uint32_t& r0, uint32_t& r1, uint32_t& r2,
                                         uint32_t& r3, uint32_t addr){
    asm volatile("ldmatrix.sync.aligned.m8n8.x4.shared.b16 {%0,%1,%2,%3}, [%4];"
        : "=r"(r0), "=r"(r1), "=r"(r2), "=r"(r3) : "r"(addr));
}
// fp16 MMA, fp32 accumulate
__device__ __forceinline__ void mma_f16(float& d0, float& d1, float& d2, float& d3,
                                        uint32_t a0, uint32_t a1, uint32_t a2, uint32_t a3,
                                        uint32_t b0, uint32_t b1){
    asm volatile("mma.sync.aligned.m16n8k16.row.col.f32.f16.f16.f32 "
        "{%0,%1,%2,%3}, {%4,%5,%6,%7}, {%8,%9}, {%0,%1,%2,%3};"
        : "+f"(d0), "+f"(d1), "+f"(d2), "+f"(d3)
        : "r"(a0), "r"(a1), "r"(a2), "r"(a3), "r"(b0), "r"(b1));
}
// fp16 hi/lo split of two floats, packed as 2x16-bit
__device__ __forceinline__ void split2(float a, float b, uint32_t& h, uint32_t& l){
    __half ha = __float2half_rn(a), hb = __float2half_rn(b);
    h = ((uint32_t)__half_as_ushort(ha)) | (((uint32_t)__half_as_ushort(hb)) << 16);
    __half la = __float2half_rn(a - __half2float(ha));
    __half lb = __float2half_rn(b - __half2float(hb));
    l = ((uint32_t)__half_as_ushort(la)) | (((uint32_t)__half_as_ushort(lb)) << 16);
}
// fp16 hi only
__device__ __forceinline__ uint32_t pack_h2(float a, float b){
    __half ha = __float2half_rn(a), hb = __float2half_rn(b);
    return ((uint32_t)__half_as_ushort(ha)) | (((uint32_t)__half_as_ushort(hb)) << 16);
}
__device__ __forceinline__ void split8(const float4& x0, const float4& x1,
                                       uint4& h, uint4& l){
    split2(x0.x, x0.y, h.x, l.x);
    split2(x0.z, x0.w, h.y, l.y);
    split2(x1.x, x1.y, h.z, l.z);
    split2(x1.z, x1.w, h.w, l.w);
}

// ---------------- one-shot split of all 7 fp32 tensors ----------------
__global__ __launch_bounds__(256) void split_all(
    const float* __restrict__ i0, const float* __restrict__ i1,
    const float* __restrict__ i2, const float* __restrict__ i3,
    const float* __restrict__ i4, const float* __restrict__ i5,
    const float* __restrict__ i6,
    __nv_bfloat16* __restrict__ h0, __nv_bfloat16* __restrict__ h1,
    __nv_bfloat16* __restrict__ h2, __nv_bfloat16* __restrict__ h3,
    __nv_bfloat16* __restrict__ h4, __nv_bfloat16* __restrict__ h5,
    __nv_bfloat16* __restrict__ h6,
    __nv_bfloat16* __restrict__ l0, __nv_bfloat16* __restrict__ l1,
    __nv_bfloat16* __restrict__ l2, __nv_bfloat16* __restrict__ l3,
    __nv_bfloat16* __restrict__ l4, __nv_bfloat16* __restrict__ l5,
    __nv_bfloat16* __restrict__ l6)
{
    const int t = blockIdx.y;
    const int n = (t < 3) ? BS_*D_ : D_*D_;
    int i = (blockIdx.x * 256 + threadIdx.x) * 4;
    if (i >= n) return;
    const float* in = (t==0)?i0:(t==1)?i1:(t==2)?i2:(t==3)?i3:(t==4)?i4:(t==5)?i5:i6;
    __nv_bfloat16* hi = (t==0)?h0:(t==1)?h1:(t==2)?h2:(t==3)?h3:(t==4)?h4:(t==5)?h5:h6;
    __nv_bfloat16* lo = (t==0)?l0:(t==1)?l1:(t==2)?l2:(t==3)?l3:(t==4)?l4:(t==5)?l5:l6;
    float4 x = *reinterpret_cast<const float4*>(in + i);
    uint32_t a0, b0, a1, b1;
    split2(x.x, x.y, a0, b0);
    split2(x.z, x.w, a1, b1);
    *reinterpret_cast<uint2*>(hi + i) = make_uint2(a0, a1);
    *reinterpret_cast<uint2*>(lo + i) = make_uint2(b0, b1);
}

// ===========================================================================
// Shared GEMM machinery: BM=128, BN=128, BK=32, 8 warps, 2-stage cp.async,
// occupancy 2, 80B padded rows. fp16 2-pass: A split hi/lo, B hi only.
// ===========================================================================
#define GEMM_CONSTS \
    constexpr int BM = 128, BN = 128, BK = 32; \
    constexpr int ROWB = 80; \
    constexpr int ATILE = BM * ROWB; \
    constexpr int BTILE = BN * ROWB; \
    constexpr int STAGE = 2 * ATILE + BTILE; \
    constexpr int WARPS_M = 2, WARPS_N = 4; \
    constexpr int MT = 4, NT = 4; \
    (void)sizeof(char[WARPS_M + WARPS_N]);

#define GEMM_ISSUE(st, Ah_p, Al_p, Bh_p, kt) do { \
    _Pragma("unroll") \
    for (int i_ = 0; i_ < 2; i_++) { \
        int row_ = l_row + i_ * 64; \
        long g_ = (long)(m0 + row_) * lda + (kt) + l_c8 * 8; \
        uint32_t o_ = so + i_ * 64 * ROWB; \
        cp_async16((st) + 0     + o_, (Ah_p) + g_); \
        cp_async16((st) + ATILE + o_, (Al_p) + g_); \
    } \
    _Pragma("unroll") \
    for (int i_ = 0; i_ < 2; i_++) { \
        int row_ = l_row + i_ * 64; \
        long g_ = (long)(n0 + row_) * ldb + (kt) + l_c8 * 8; \
        uint32_t o_ = so + i_ * 64 * ROWB; \
        cp_async16((st) + 2*ATILE + o_, (Bh_p) + g_); \
    } \
} while(0)

#define GEMM_COMPUTE(st) do { \
    const uint32_t a_row_ = m_warp + (lane & 15); \
    const uint32_t a_k8_  = (lane >> 4) * 16; \
    const uint32_t b_row_ = n_warp + (lane & 7) + ((lane >> 4) & 1) * 8; \
    const uint32_t b_k8_  = ((lane >> 3) & 1) * 16; \
    _Pragma("unroll") \
    for (int ks_ = 0; ks_ < 2; ks_++) { \
        const uint32_t kb_ = ks_ * 32; \
        uint32_t ah_[MT][4], al_[MT][4]; \
        _Pragma("unroll") \
        for (int im_ = 0; im_ < MT; im_++) { \
            uint32_t ad_ = (st) + (a_row_ + im_ * 16) * ROWB + kb_ + a_k8_; \
            ldmat_x4(ah_[im_][0], ah_[im_][1], ah_[im_][2], ah_[im_][3], ad_); \
            ad_ += ATILE; \
            ldmat_x4(al_[im_][0], al_[im_][1], al_[im_][2], al_[im_][3], ad_); \
        } \
        uint32_t bh_[NT][2]; \
        _Pragma("unroll") \
        for (int j2_ = 0; j2_ < NT/2; j2_++) { \
            uint32_t ad_ = (st) + 2*ATILE + (b_row_ + j2_ * 16) * ROWB + kb_ + b_k8_; \
            ldmat_x4(bh_[j2_*2][0], bh_[j2_*2][1], bh_[j2_*2+1][0], bh_[j2_*2+1][1], ad_); \
        } \
        _Pragma("unroll") \
        for (int im_ = 0; im_ < MT; im_++) \
        _Pragma("unroll") \
        for (int jn_ = 0; jn_ < NT; jn_++) { \
            float* d_ = acc[im_][jn_]; \
            mma_f16(d_[0], d_[1], d_[2], d_[3], \
                    ah_[im_][0], ah_[im_][1], ah_[im_][2], ah_[im_][3], \
                    bh_[jn_][0], bh_[jn_][1]); \
            mma_f16(d_[0], d_[1], d_[2], d_[3], \
                    al_[im_][0], al_[im_][1], al_[im_][2], al_[im_][3], \
                    bh_[jn_][0], bh_[jn_][1]); \
        } \
    } \
} while(0)

#define GEMM_MAINLOOP(Ah_p, Al_p, Bh_p) do { \
    const int NI_ = K / BK; \
    GEMM_ISSUE(sbase, Ah_p, Al_p, Bh_p, 0); \
    CP_COMMIT(); \
    if (NI_ > 1) GEMM_ISSUE(sbase + STAGE, Ah_p, Al_p, Bh_p, BK); \
    CP_COMMIT(); \
    for (int it_ = 0; it_ < NI_; it_++) { \
        CP_WAIT1(); \
        __syncthreads(); \
        GEMM_COMPUTE(sbase + (it_ & 1) * STAGE); \
        __syncthreads(); \
        if (it_ + 2 < NI_) \
            GEMM_ISSUE(sbase + (it_ & 1) * STAGE, Ah_p, Al_p, Bh_p, (it_ + 2) * BK); \
        CP_COMMIT(); \
    } \
} while(0)

#define GEMM_PREAMBLE \
    GEMM_CONSTS \
    extern __shared__ char smem[]; \
    const uint32_t sbase = smem_u32(smem); \
    const int tid  = threadIdx.x; \
    const int lane = tid & 31; \
    const int wid  = tid >> 5; \
    const int m_warp = (wid % WARPS_M) * (BM / WARPS_M); \
    const int n_warp = (wid / WARPS_M) * (BN / WARPS_N); \
    const int l_row = tid >> 2; \
    const int l_c8  = tid & 3; \
    const uint32_t so = l_row * ROWB + l_c8 * 16; \
    float acc[MT][NT][4]; \
    _Pragma("unroll") \
    for (int i_ = 0; i_ < MT; i_++) \
    _Pragma("unroll") \
    for (int j_ = 0; j_ < NT; j_++) \
    _Pragma("unroll") \
    for (int r_ = 0; r_ < 4; r_++) acc[i_][j_][r_] = 0.0f;

// ---------------------------------------------------------------------------
// Merged Q/K/V projection GEMM. proj 0,1: split store. proj 2: transposed.
// ---------------------------------------------------------------------------
__global__ __launch_bounds__(256, 2) void mma_gemm_qkv(
    const __nv_bfloat16* __restrict__ iQh, const __nv_bfloat16* __restrict__ iQl,
    const __nv_bfloat16* __restrict__ iKh, const __nv_bfloat16* __restrict__ iKl,
    const __nv_bfloat16* __restrict__ iVh, const __nv_bfloat16* __restrict__ iVl,
    const __nv_bfloat16* __restrict__ wqh,
    const __nv_bfloat16* __restrict__ wkh,
    const __nv_bfloat16* __restrict__ wvh,
    __nv_bfloat16* __restrict__ qh, __nv_bfloat16* __restrict__ ql,
    __nv_bfloat16* __restrict__ kh, __nv_bfloat16* __restrict__ kl,
    __nv_bfloat16* __restrict__ vth, __nv_bfloat16* __restrict__ vtl)
{
    GEMM_PREAMBLE
    const int K = D_, lda = D_, ldb = D_, ldc = D_;
    const int m0 = blockIdx.y * BM;
    const int n0 = blockIdx.x * BN;
    const int proj = blockIdx.z;

    const __nv_bfloat16* A_h = (proj==0) ? iQh : (proj==1) ? iKh : iVh;
    const __nv_bfloat16* A_l = (proj==0) ? iQl : (proj==1) ? iKl : iVl;
    const __nv_bfloat16* B_h = (proj==0) ? wqh : (proj==1) ? wkh : wvh;
    __nv_bfloat16* C_h = (proj==0) ? qh : (proj==1) ? kh : vth;
    __nv_bfloat16* C_l = (proj==0) ? ql : (proj==1) ? kl : vtl;

    GEMM_MAINLOOP(A_h, A_l, B_h);

    const int rbase = m0 + m_warp + (lane >> 2);
    const int cbase = n0 + n_warp + (lane & 3) * 2;
    if (proj < 2) {
#pragma unroll
        for (int im = 0; im < MT; im++)
#pragma unroll
            for (int jn = 0; jn < NT; jn++) {
                const float* d = acc[im][jn];
                int r0 = rbase + im * 16;
                int c  = cbase + jn * 8;
                uint32_t h, l;
                split2(d[0], d[1], h, l);
                long b0a = (long)r0 * ldc + c;
                *reinterpret_cast<uint32_t*>(C_h + b0a) = h;
                *reinterpret_cast<uint32_t*>(C_l + b0a) = l;
                split2(d[2], d[3], h, l);
                long b1a = (long)(r0 + 8) * ldc + c;
                *reinterpret_cast<uint32_t*>(C_h + b1a) = h;
                *reinterpret_cast<uint32_t*>(C_l + b1a) = l;
            }
    } else {
#pragma unroll
        for (int im = 0; im < MT; im++)
#pragma unroll
            for (int jn = 0; jn < NT; jn++) {
                const float* d = acc[im][jn];
                int r0 = rbase + im * 16;
                int c  = cbase + jn * 8;
#pragma unroll
                for (int e = 0; e < 4; e++) {
                    int m = r0 + (e >> 1) * 8;
                    int n = c + (e & 1);
                    float f = d[e];
                    __half hv = __float2half_rn(f);
                    __half lv = __float2half_rn(f - __half2float(hv));
                    int b2 = m >> 11, s2 = m & (S_ - 1);
                    int hidx = n >> 6, hd = n & 63;
                    long addr = (((long)b2 * H_ + hidx) * HD_ + hd) * S_ + s2;
                    *reinterpret_cast<unsigned short*>(C_h + addr) = __half_as_ushort(hv);
                    *reinterpret_cast<unsigned short*>(C_l + addr) = __half_as_ushort(lv);
                }
            }
    }
}

// ---------------------------------------------------------------------------
// Generic batched GEMM, fp32 epilogue (*alpha). Scores + final GEMM.
// ---------------------------------------------------------------------------
__global__ __launch_bounds__(256, 2) void mma_gemm_f32(
    const __nv_bfloat16* __restrict__ Ah, const __nv_bfloat16* __restrict__ Al,
    const __nv_bfloat16* __restrict__ Bh,
    float* __restrict__ C,
    int K, int lda, int ldb, int ldc,
    long offAb, long offAh_, long offBb, long offBh_, long offCb, long offCh_,
    int Hdiv, float alpha)
{
    GEMM_PREAMBLE
    const int z = blockIdx.z;
    const int bb = z / Hdiv, hh = z % Hdiv;
    const __nv_bfloat16* A_h = Ah + (long)bb * offAb + (long)hh * offAh_;
    const __nv_bfloat16* A_l = Al + (long)bb * offAb + (long)hh * offAh_;
    const __nv_bfloat16* B_h = Bh + (long)bb * offBb + (long)hh * offBh_;
    const long coff = (long)bb * offCb + (long)hh * offCh_;
    const int m0 = blockIdx.y * BM;
    const int n0 = blockIdx.x * BN;

    GEMM_MAINLOOP(A_h, A_l, B_h);

    const int rbase = m0 + m_warp + (lane >> 2);
    const int cbase = n0 + n_warp + (lane & 3) * 2;
#pragma unroll
    for (int im = 0; im < MT; im++)
#pragma unroll
        for (int jn = 0; jn < NT; jn++) {
            const float* d = acc[im][jn];
            int r0 = rbase + im * 16;
            int c  = cbase + jn * 8;
            *reinterpret_cast<float2*>(C + coff + (long)r0 * ldc + c) =
                make_float2(d[0] * alpha, d[1] * alpha);
            *reinterpret_cast<float2*>(C + coff + (long)(r0 + 8) * ldc + c) =
                make_float2(d[2] * alpha, d[3] * alpha);
        }
}

// ---------------------------------------------------------------------------
// AV GEMM: A = softmax weights fp32 -> fp16 HI ONLY (single pass; weights in
// [0,1], adds ~2.8e-4 RMS rel err). B = v^T fp16-hi. BM=128, BN=64, BK=32.
// Half the MMAs of the 2-pass version; AV becomes read-bound.
// ---------------------------------------------------------------------------
__global__ __launch_bounds__(256, 2) void mma_gemm_av(
    const float* __restrict__ Afp,
    const __nv_bfloat16* __restrict__ Bh,
    __nv_bfloat16* __restrict__ Chi, __nv_bfloat16* __restrict__ Clo,
    int K, int lda, int ldb, int ldc,
    long offAb, long offAh_, long offBb, long offBh_, long offCb, long offCh_,
    int Hdiv)
{
    constexpr int BM = 128, BN = 64, BK = 32;
    constexpr int ROWB = 80;
    constexpr int ATILE = BM * ROWB;
    constexpr int BTILE = BN * ROWB;
    constexpr int STAGE = ATILE + BTILE;          // hi-only A + hi B
    constexpr int AF4 = 2, BF4 = 1;
    constexpr int WARPS_M = 4, WARPS_N = 2;
    constexpr int MT = 2, NT = 4;

    extern __shared__ char smem[];
    const uint32_t sbase = smem_u32(smem);

    const int tid  = threadIdx.x;
    const int lane = tid & 31;
    const int wid  = tid >> 5;

    const int z = blockIdx.z;
    const int bb = z / Hdiv, hh = z % Hdiv;
    const float* A = Afp + (long)bb * offAb + (long)hh * offAh_;
    const __nv_bfloat16* B_h = Bh + (long)bb * offBb + (long)hh * offBh_;
    const long coff = (long)bb * offCb + (long)hh * offCh_;

    const int m0 = blockIdx.y * BM;
    const int n0 = blockIdx.x * BN;

    const int m_warp = (wid % WARPS_M) * (BM / WARPS_M);
    const int n_warp = (wid / WARPS_M) * (BN / WARPS_N);

    const uint32_t OFF_AH = 0, OFF_BH = ATILE;

    float acc[MT][NT][4];
#pragma unroll
    for (int i = 0; i < MT; i++)
#pragma unroll
        for (int j = 0; j < NT; j++)
#pragma unroll
            for (int r = 0; r < 4; r++) acc[i][j][r] = 0.0f;

    uint4 rAh[AF4], rBh[BF4];

    auto gload = [&](int it) {
        const int kt = it * BK;
#pragma unroll
        for (int i = 0; i < AF4; i++) {
            int f4 = tid + i * 256;
            int row = f4 >> 2, c8 = f4 & 3;
            long g = (long)(m0 + row) * lda + kt + c8 * 8;
            float4 x0 = *reinterpret_cast<const float4*>(A + g);
            float4 x1 = *reinterpret_cast<const float4*>(A + g + 4);
            rAh[i] = make_uint4(pack_h2(x0.x, x0.y), pack_h2(x0.z, x0.w),
                                pack_h2(x1.x, x1.y), pack_h2(x1.z, x1.w));
        }
#pragma unroll
        for (int i = 0; i < BF4; i++) {
            int f4 = tid + i * 256;
            int row = f4 >> 2, c8 = f4 & 3;
            long g = (long)(n0 + row) * ldb + kt + c8 * 8;
            rBh[i] = *reinterpret_cast<const uint4*>(B_h + g);
        }
    };

    auto sstore = [&](int buf) {
        char* st = smem + buf * STAGE;
#pragma unroll
        for (int i = 0; i < AF4; i++) {
            int f4 = tid + i * 256;
            int row = f4 >> 2, c8 = f4 & 3;
            uint32_t o = row * ROWB + c8 * 16;
            *reinterpret_cast<uint4*>(st + OFF_AH + o) = rAh[i];
        }
#pragma unroll
        for (int i = 0; i < BF4; i++) {
            int f4 = tid + i * 256;
            int row = f4 >> 2, c8 = f4 & 3;
            uint32_t o = row * ROWB + c8 * 16;
            *reinterpret_cast<uint4*>(st + OFF_BH + o) = rBh[i];
        }
    };

    auto compute = [&](int buf) {
        const uint32_t st = sbase + buf * STAGE;
        const uint32_t a_row = m_warp + (lane & 15);
        const uint32_t a_k8  = (lane >> 4) * 16;
        const uint32_t b_row = n_warp + (lane & 7) + ((lane >> 4) & 1) * 8;
        const uint32_t b_k8  = ((lane >> 3) & 1) * 16;
#pragma unroll
        for (int ks = 0; ks < 2; ks++) {
            const uint32_t kbyte = ks * 32;
            uint32_t ah[MT][4];
#pragma unroll
            for (int im = 0; im < MT; im++) {
                uint32_t addr = st + OFF_AH + (a_row + im * 16) * ROWB + kbyte + a_k8;
                ldmat_x4(ah[im][0], ah[im][1], ah[im][2], ah[im][3], addr);
            }
            uint32_t bh[NT][2];
#pragma unroll
            for (int j2 = 0; j2 < NT / 2; j2++) {
                uint32_t addr = st + OFF_BH + (b_row + j2 * 16) * ROWB + kbyte + b_k8;
                ldmat_x4(bh[j2*2][0], bh[j2*2][1], bh[j2*2+1][0], bh[j2*2+1][1], addr);
            }
#pragma unroll
            for (int im = 0; im < MT; im++)
#pragma unroll
                for (int jn = 0; jn < NT; jn++) {
                    float* d = acc[im][jn];
                    mma_f16(d[0], d[1], d[2], d[3],
                            ah[im][0], ah[im][1], ah[im][2], ah[im][3],
                            bh[jn][0], bh[jn][1]);
                }
        }
    };

    const int NI = K / BK;
    gload(0);
    sstore(0);
    __syncthreads();
    int buf = 0;
    for (int it = 1; it < NI; it++) {
        gload(it);
        compute(buf);
        sstore(buf ^ 1);
        __syncthreads();
        buf ^= 1;
    }
    compute(buf);

    const int rbase = m0 + m_warp + (lane >> 2);
    const int cbase = n0 + n_warp + (lane & 3) * 2;
#pragma unroll
    for (int im = 0; im < MT; im++) {
#pragma unroll
        for (int jn = 0; jn < NT; jn++) {
            const float* d = acc[im][jn];
            int r0 = rbase + im * 16;
            int c  = cbase + jn * 8;
            uint32_t h, l;
            split2(d[0], d[1], h, l);
            long b0a = coff + (long)r0 * ldc + c;
            *reinterpret_cast<uint32_t*>(Chi + b0a) = h;
            *reinterpret_cast<uint32_t*>(Clo + b0a) = l;
            split2(d[2], d[3], h, l);
            long b1a = coff + (long)(r0 + 8) * ldc + c;
            *reinterpret_cast<uint32_t*>(Chi + b1a) = h;
            *reinterpret_cast<uint32_t*>(Clo + b1a) = l;
        }
    }
}

// ---------------------------------------------------------------------------
// Register-resident softmax: one read + one write per element.
// ---------------------------------------------------------------------------
__global__ __launch_bounds__(256) void softmax_rows2048(float* __restrict__ W)
{
    float4* p = reinterpret_cast<float4*>(W + (long)blockIdx.x * S_);
    const int t = threadIdx.x;
    const int lane = t & 31, warp = t >> 5;

    __shared__ float red[8];

    float4 x0 = p[t];
    float4 x1 = p[t + 256];

    float m = fmaxf(fmaxf(fmaxf(x0.x, x0.y), fmaxf(x0.z, x0.w)),
                    fmaxf(fmaxf(x1.x, x1.y), fmaxf(x1.z, x1.w)));
#pragma unroll
    for (int s = 16; s > 0; s >>= 1)
        m = fmaxf(m, __shfl_xor_sync(0xFFFFFFFFu, m, s));
    if (lane == 0) red[warp] = m;
    __syncthreads();
    {
        float v = red[lane & 7];
#pragma unroll
        for (int s = 4; s > 0; s >>= 1)
            v = fmaxf(v, __shfl_xor_sync(0xFFFFFFFFu, v, s));
        m = v;
    }

    x0.x = __expf(x0.x - m); x0.y = __expf(x0.y - m);
    x0.z = __expf(x0.z - m); x0.w = __expf(x0.w - m);
    x1.x = __expf(x1.x - m); x1.y = __expf(x1.y - m);
    x1.z = __expf(x1.z - m); x1.w = __expf(x1.w - m);
    float sum = (x0.x + x0.y) + (x0.z + x0.w) + (x1.x + x1.y) + (x1.z + x1.w);
#pragma unroll
    for (int s = 16; s > 0; s >>= 1)
        sum += __shfl_xor_sync(0xFFFFFFFFu, sum, s);
    __syncthreads();
    if (lane == 0) red[warp] = sum;
    __syncthreads();
    {
        float v = red[lane & 7];
#pragma unroll
        for (int s = 4; s > 0; s >>= 1)
            v += __shfl_xor_sync(0xFFFFFFFFu, v, s);
        sum = v;
    }

    const float inv = 1.0f / sum;
    x0.x *= inv; x0.y *= inv; x0.z *= inv; x0.w *= inv;
    x1.x *= inv; x1.y *= inv; x1.z *= inv; x1.w *= inv;
    p[t] = x0;
    p[t + 256] = x1;
}

// ---------------------------------------------------------------------------
extern "C" void kernel_launch(void* const* d_in, const int* in_sizes, int n_in,
                              void* d_out, int out_size)
{
    const float* Q  = (const float*)d_in[0];
    const float* K  = (const float*)d_in[1];
    const float* V  = (const float*)d_in[2];
    const float* Wq = (const float*)d_in[3];
    const float* Wk = (const float*)d_in[4];
    const float* Wv = (const float*)d_in[5];
    const float* Wo = (const float*)d_in[6];

    float* out = (float*)d_out;
    float* final_out = out;                       // [B,S,D]
    float* weights   = out + (long)B_ * S_ * D_;  // [B,H,S,S]

    __nv_bfloat16 *iQh,*iQl,*iKh,*iKl,*iVh,*iVl;
    __nv_bfloat16 *wqh,*wql,*wkh,*wkl,*wvh,*wvl,*woh,*wol;
    __nv_bfloat16 *qh,*ql,*kh,*kl,*vth,*vtl,*cath,*catl;
    cudaGetSymbolAddress((void**)&iQh, g_iQh); cudaGetSymbolAddress((void**)&iQl, g_iQl);
    cudaGetSymbolAddress((void**)&iKh, g_iKh); cudaGetSymbolAddress((void**)&iKl, g_iKl);
    cudaGetSymbolAddress((void**)&iVh, g_iVh); cudaGetSymbolAddress((void**)&iVl, g_iVl);
    cudaGetSymbolAddress((void**)&wqh, g_wqh); cudaGetSymbolAddress((void**)&wql, g_wql);
    cudaGetSymbolAddress((void**)&wkh, g_wkh); cudaGetSymbolAddress((void**)&wkl, g_wkl);
    cudaGetSymbolAddress((void**)&wvh, g_wvh); cudaGetSymbolAddress((void**)&wvl, g_wvl);
    cudaGetSymbolAddress((void**)&woh, g_woh); cudaGetSymbolAddress((void**)&wol, g_wol);
    cudaGetSymbolAddress((void**)&qh,  g_qh);  cudaGetSymbolAddress((void**)&ql,  g_ql);
    cudaGetSymbolAddress((void**)&kh,  g_kh);  cudaGetSymbolAddress((void**)&kl,  g_kl);
    cudaGetSymbolAddress((void**)&vth, g_vth); cudaGetSymbolAddress((void**)&vtl, g_vtl);
    cudaGetSymbolAddress((void**)&cath,g_cath);cudaGetSymbolAddress((void**)&catl,g_catl);

    constexpr int ROWB = 80;
    constexpr int SM_G  = 2 * (2 * 128 * ROWB + 128 * ROWB);  // 61440
    constexpr int SM_AV = 2 * (128 * ROWB + 64 * ROWB);       // 30720

    cudaFuncSetAttribute(mma_gemm_qkv, cudaFuncAttributeMaxDynamicSharedMemorySize, SM_G);
    cudaFuncSetAttribute(mma_gemm_f32, cudaFuncAttributeMaxDynamicSharedMemorySize, SM_G);
    cudaFuncSetAttribute(mma_gemm_av,  cudaFuncAttributeMaxDynamicSharedMemorySize, SM_AV);

    // 0) split all fp32 inputs into fp16 hi/lo (single launch)
    {
        dim3 g(BS_*D_/1024, 7, 1);
        split_all<<<g, 256>>>(Q, K, V, Wq, Wk, Wv, Wo,
                              iQh, iKh, iVh, wqh, wkh, wvh, woh,
                              iQl, iKl, iVl, wql, wkl, wvl, wol);
    }

    // 1) merged projections (B = weight hi only)
    {
        dim3 g(D_/128, BS_/128, 3);
        mma_gemm_qkv<<<g, 256, SM_G>>>(iQh, iQl, iKh, iKl, iVh, iVl,
                                       wqh, wkh, wvh,
                                       qh, ql, kh, kl, vth, vtl);
    }

    // 2) scores = 0.125 * q @ k^T -> weights (fp32, pre-softmax)
    {
        dim3 g(S_/128, S_/128, B_*H_);
        mma_gemm_f32<<<g, 256, SM_G>>>(qh, ql, kh, weights,
            HD_, D_, D_, S_,
            (long)S_*D_, (long)HD_, (long)S_*D_, (long)HD_,
            (long)H_*S_*S_, (long)S_*S_, H_, 0.125f);
    }

    // 3) softmax in place
    softmax_rows2048<<<B_*H_*S_, 256>>>(weights);

    // 4) cat = softmax(scores) @ v  (A single-pass fp16)
    {
        dim3 g(1, S_/128, B_*H_);
        mma_gemm_av<<<g, 256, SM_AV>>>(weights, vth,
            cath, catl,
            S_, S_, S_, D_,
            (long)H_*S_*S_, (long)S_*S_,
            (long)H_*HD_*S_, (long)HD_*S_,
            (long)S_*D_, (long)HD_, H_);
    }

    // 5) final = cat @ Wo^T (fp32 out)
    {
        dim3 g(D_/128, BS_/128, 1);
        mma_gemm_f32<<<g, 256, SM_G>>>(cath, catl, woh, final_out,
            D_, D_, D_, D_, 0,0,0,0,0,0, 1, 1.0f);
    }
}

// round 16
// speedup vs baseline: 1.3228x; 1.0569x over previous
#include <cuda_runtime.h>
#include <cuda_bf16.h>
#include <cuda_fp16.h>
#include <stdint.h>
#include <math.h>

#define B_ 2
#define S_ 2048
#define D_ 1024
#define H_ 16
#define HD_ 64
#define BS_ (B_*S_)

// ---------------- 16-bit split scratch (raw storage; format = fp16 hi/lo) ---
__device__ __nv_bfloat16 g_iQh[BS_*D_], g_iQl[BS_*D_];
__device__ __nv_bfloat16 g_iKh[BS_*D_], g_iKl[BS_*D_];
__device__ __nv_bfloat16 g_iVh[BS_*D_], g_iVl[BS_*D_];
__device__ __nv_bfloat16 g_wqh[D_*D_], g_wql[D_*D_];
__device__ __nv_bfloat16 g_wkh[D_*D_], g_wkl[D_*D_];
__device__ __nv_bfloat16 g_wvh[D_*D_], g_wvl[D_*D_];
__device__ __nv_bfloat16 g_woh[D_*D_], g_wol[D_*D_];
__device__ __nv_bfloat16 g_qh[BS_*D_], g_ql[BS_*D_];
__device__ __nv_bfloat16 g_kh[BS_*D_], g_kl[BS_*D_];
__device__ __nv_bfloat16 g_vth[BS_*D_], g_vtl[BS_*D_];   // [B,H,HD,S]
__device__ __nv_bfloat16 g_cath[BS_*D_], g_catl[BS_*D_]; // [B,S,D]

// ---------------- helpers ----------------
__device__ __forceinline__ uint32_t smem_u32(const void* p){
    uint32_t a;
    asm("{ .reg .u64 t; cvta.to.shared.u64 t, %1; cvt.u32.u64 %0, t; }" : "=r"(a) : "l"(p));
    return a;
}
__device__ __forceinline__ void cp_async16(uint32_t saddr, const void* g){
    asm volatile("cp.async.cg.shared.global [%0], [%1], 16;" :: "r"(saddr), "l"(g));
}
#define CP_COMMIT() asm volatile("cp.async.commit_group;" ::: "memory")
#define CP_WAIT1()  asm volatile("cp.async.wait_group 1;"  ::: "memory")

__device__ __forceinline__ void ldmat_x4(uint32_t& r0, uint32_t& r1, uint32_t& r2,
                                         uint32_t& r3, uint32_t addr){
    asm volatile("ldmatrix.sync.aligned.m8n8.x4.shared.b16 {%0,%1,%2,%3}, [%4];"
        : "=r"(r0), "=r"(r1), "=r"(r2), "=r"(r3) : "r"(addr));
}
// fp16 MMA, fp32 accumulate
__device__ __forceinline__ void mma_f16(float& d0, float& d1, float& d2, float& d3,
                                        uint32_t a0, uint32_t a1, uint32_t a2, uint32_t a3,
                                        uint32_t b0, uint32_t b1){
    asm volatile("mma.sync.aligned.m16n8k16.row.col.f32.f16.f16.f32 "
        "{%0,%1,%2,%3}, {%4,%5,%6,%7}, {%8,%9}, {%0,%1,%2,%3};"
        : "+f"(d0), "+f"(d1), "+f"(d2), "+f"(d3)
        : "r"(a0), "r"(a1), "r"(a2), "r"(a3), "r"(b0), "r"(b1));
}
// fp16 hi/lo split of two floats, packed as 2x16-bit
__device__ __forceinline__ void split2(float a, float b, uint32_t& h, uint32_t& l){
    __half ha = __float2half_rn(a), hb = __float2half_rn(b);
    h = ((uint32_t)__half_as_ushort(ha)) | (((uint32_t)__half_as_ushort(hb)) << 16);
    __half la = __float2half_rn(a - __half2float(ha));
    __half lb = __float2half_rn(b - __half2float(hb));
    l = ((uint32_t)__half_as_ushort(la)) | (((uint32_t)__half_as_ushort(lb)) << 16);
}
// fp16 hi only
__device__ __forceinline__ uint32_t pack_h2(float a, float b){
    __half ha = __float2half_rn(a), hb = __float2half_rn(b);
    return ((uint32_t)__half_as_ushort(ha)) | (((uint32_t)__half_as_ushort(hb)) << 16);
}
__device__ __forceinline__ void split8(const float4& x0, const float4& x1,
                                       uint4& h, uint4& l){
    split2(x0.x, x0.y, h.x, l.x);
    split2(x0.z, x0.w, h.y, l.y);
    split2(x1.x, x1.y, h.z, l.z);
    split2(x1.z, x1.w, h.w, l.w);
}

// ---------------- one-shot split of all 7 fp32 tensors ----------------
__global__ __launch_bounds__(256) void split_all(
    const float* __restrict__ i0, const float* __restrict__ i1,
    const float* __restrict__ i2, const float* __restrict__ i3,
    const float* __restrict__ i4, const float* __restrict__ i5,
    const float* __restrict__ i6,
    __nv_bfloat16* __restrict__ h0, __nv_bfloat16* __restrict__ h1,
    __nv_bfloat16* __restrict__ h2, __nv_bfloat16* __restrict__ h3,
    __nv_bfloat16* __restrict__ h4, __nv_bfloat16* __restrict__ h5,
    __nv_bfloat16* __restrict__ h6,
    __nv_bfloat16* __restrict__ l0, __nv_bfloat16* __restrict__ l1,
    __nv_bfloat16* __restrict__ l2, __nv_bfloat16* __restrict__ l3,
    __nv_bfloat16* __restrict__ l4, __nv_bfloat16* __restrict__ l5,
    __nv_bfloat16* __restrict__ l6)
{
    const int t = blockIdx.y;
    const int n = (t < 3) ? BS_*D_ : D_*D_;
    int i = (blockIdx.x * 256 + threadIdx.x) * 4;
    if (i >= n) return;
    const float* in = (t==0)?i0:(t==1)?i1:(t==2)?i2:(t==3)?i3:(t==4)?i4:(t==5)?i5:i6;
    __nv_bfloat16* hi = (t==0)?h0:(t==1)?h1:(t==2)?h2:(t==3)?h3:(t==4)?h4:(t==5)?h5:h6;
    __nv_bfloat16* lo = (t==0)?l0:(t==1)?l1:(t==2)?l2:(t==3)?l3:(t==4)?l4:(t==5)?l5:l6;
    float4 x = *reinterpret_cast<const float4*>(in + i);
    uint32_t a0, b0, a1, b1;
    split2(x.x, x.y, a0, b0);
    split2(x.z, x.w, a1, b1);
    *reinterpret_cast<uint2*>(hi + i) = make_uint2(a0, a1);
    *reinterpret_cast<uint2*>(lo + i) = make_uint2(b0, b1);
}

// ===========================================================================
// Shared GEMM machinery: BM=128, BN=128, BK=32, 8 warps, 2-stage cp.async,
// occupancy 2, 80B padded rows. APASS = 2: A hi/lo (2 MMAs); 1: A hi only.
// B is always hi-only fp16.
// ===========================================================================
#define GEMM_CONSTS(AP_) \
    constexpr int APASS = AP_; \
    constexpr int BM = 128, BN = 128, BK = 32; \
    constexpr int ROWB = 80; \
    constexpr int ATILE = BM * ROWB; \
    constexpr int BTILE = BN * ROWB; \
    constexpr int STAGE = APASS * ATILE + BTILE; \
    constexpr int WARPS_M = 2, WARPS_N = 4; \
    constexpr int MT = 4, NT = 4; \
    (void)sizeof(char[WARPS_M + WARPS_N]);

#define GEMM_ISSUE(st, Ah_p, Al_p, Bh_p, kt) do { \
    _Pragma("unroll") \
    for (int i_ = 0; i_ < 2; i_++) { \
        int row_ = l_row + i_ * 64; \
        long g_ = (long)(m0 + row_) * lda + (kt) + l_c8 * 8; \
        uint32_t o_ = so + i_ * 64 * ROWB; \
        cp_async16((st) + 0 + o_, (Ah_p) + g_); \
        if (APASS == 2) cp_async16((st) + ATILE + o_, (Al_p) + g_); \
    } \
    _Pragma("unroll") \
    for (int i_ = 0; i_ < 2; i_++) { \
        int row_ = l_row + i_ * 64; \
        long g_ = (long)(n0 + row_) * ldb + (kt) + l_c8 * 8; \
        uint32_t o_ = so + i_ * 64 * ROWB; \
        cp_async16((st) + APASS*ATILE + o_, (Bh_p) + g_); \
    } \
} while(0)

#define GEMM_COMPUTE(st) do { \
    const uint32_t a_row_ = m_warp + (lane & 15); \
    const uint32_t a_k8_  = (lane >> 4) * 16; \
    const uint32_t b_row_ = n_warp + (lane & 7) + ((lane >> 4) & 1) * 8; \
    const uint32_t b_k8_  = ((lane >> 3) & 1) * 16; \
    _Pragma("unroll") \
    for (int ks_ = 0; ks_ < 2; ks_++) { \
        const uint32_t kb_ = ks_ * 32; \
        uint32_t ah_[MT][4], al_[MT][4]; \
        _Pragma("unroll") \
        for (int im_ = 0; im_ < MT; im_++) { \
            uint32_t ad_ = (st) + (a_row_ + im_ * 16) * ROWB + kb_ + a_k8_; \
            ldmat_x4(ah_[im_][0], ah_[im_][1], ah_[im_][2], ah_[im_][3], ad_); \
            if (APASS == 2) { \
                ad_ += ATILE; \
                ldmat_x4(al_[im_][0], al_[im_][1], al_[im_][2], al_[im_][3], ad_); \
            } \
        } \
        uint32_t bh_[NT][2]; \
        _Pragma("unroll") \
        for (int j2_ = 0; j2_ < NT/2; j2_++) { \
            uint32_t ad_ = (st) + APASS*ATILE + (b_row_ + j2_ * 16) * ROWB + kb_ + b_k8_; \
            ldmat_x4(bh_[j2_*2][0], bh_[j2_*2][1], bh_[j2_*2+1][0], bh_[j2_*2+1][1], ad_); \
        } \
        _Pragma("unroll") \
        for (int im_ = 0; im_ < MT; im_++) \
        _Pragma("unroll") \
        for (int jn_ = 0; jn_ < NT; jn_++) { \
            float* d_ = acc[im_][jn_]; \
            mma_f16(d_[0], d_[1], d_[2], d_[3], \
                    ah_[im_][0], ah_[im_][1], ah_[im_][2], ah_[im_][3], \
                    bh_[jn_][0], bh_[jn_][1]); \
            if (APASS == 2) \
                mma_f16(d_[0], d_[1], d_[2], d_[3], \
                        al_[im_][0], al_[im_][1], al_[im_][2], al_[im_][3], \
                        bh_[jn_][0], bh_[jn_][1]); \
        } \
    } \
} while(0)

#define GEMM_MAINLOOP(Ah_p, Al_p, Bh_p) do { \
    const int NI_ = K / BK; \
    GEMM_ISSUE(sbase, Ah_p, Al_p, Bh_p, 0); \
    CP_COMMIT(); \
    if (NI_ > 1) GEMM_ISSUE(sbase + STAGE, Ah_p, Al_p, Bh_p, BK); \
    CP_COMMIT(); \
    for (int it_ = 0; it_ < NI_; it_++) { \
        CP_WAIT1(); \
        __syncthreads(); \
        GEMM_COMPUTE(sbase + (it_ & 1) * STAGE); \
        __syncthreads(); \
        if (it_ + 2 < NI_) \
            GEMM_ISSUE(sbase + (it_ & 1) * STAGE, Ah_p, Al_p, Bh_p, (it_ + 2) * BK); \
        CP_COMMIT(); \
    } \
} while(0)

#define GEMM_PREAMBLE(AP_) \
    GEMM_CONSTS(AP_) \
    extern __shared__ char smem[]; \
    const uint32_t sbase = smem_u32(smem); \
    const int tid  = threadIdx.x; \
    const int lane = tid & 31; \
    const int wid  = tid >> 5; \
    const int m_warp = (wid % WARPS_M) * (BM / WARPS_M); \
    const int n_warp = (wid / WARPS_M) * (BN / WARPS_N); \
    const int l_row = tid >> 2; \
    const int l_c8  = tid & 3; \
    const uint32_t so = l_row * ROWB + l_c8 * 16; \
    float acc[MT][NT][4]; \
    _Pragma("unroll") \
    for (int i_ = 0; i_ < MT; i_++) \
    _Pragma("unroll") \
    for (int j_ = 0; j_ < NT; j_++) \
    _Pragma("unroll") \
    for (int r_ = 0; r_ < 4; r_++) acc[i_][j_][r_] = 0.0f;

// ---------------------------------------------------------------------------
// Merged Q/K/V projection GEMM (2-pass A: inputs stay near-exact).
// ---------------------------------------------------------------------------
__global__ __launch_bounds__(256, 2) void mma_gemm_qkv(
    const __nv_bfloat16* __restrict__ iQh, const __nv_bfloat16* __restrict__ iQl,
    const __nv_bfloat16* __restrict__ iKh, const __nv_bfloat16* __restrict__ iKl,
    const __nv_bfloat16* __restrict__ iVh, const __nv_bfloat16* __restrict__ iVl,
    const __nv_bfloat16* __restrict__ wqh,
    const __nv_bfloat16* __restrict__ wkh,
    const __nv_bfloat16* __restrict__ wvh,
    __nv_bfloat16* __restrict__ qh, __nv_bfloat16* __restrict__ ql,
    __nv_bfloat16* __restrict__ kh, __nv_bfloat16* __restrict__ kl,
    __nv_bfloat16* __restrict__ vth, __nv_bfloat16* __restrict__ vtl)
{
    GEMM_PREAMBLE(2)
    const int K = D_, lda = D_, ldb = D_, ldc = D_;
    const int m0 = blockIdx.y * BM;
    const int n0 = blockIdx.x * BN;
    const int proj = blockIdx.z;

    const __nv_bfloat16* A_h = (proj==0) ? iQh : (proj==1) ? iKh : iVh;
    const __nv_bfloat16* A_l = (proj==0) ? iQl : (proj==1) ? iKl : iVl;
    const __nv_bfloat16* B_h = (proj==0) ? wqh : (proj==1) ? wkh : wvh;
    __nv_bfloat16* C_h = (proj==0) ? qh : (proj==1) ? kh : vth;
    __nv_bfloat16* C_l = (proj==0) ? ql : (proj==1) ? kl : vtl;

    GEMM_MAINLOOP(A_h, A_l, B_h);

    const int rbase = m0 + m_warp + (lane >> 2);
    const int cbase = n0 + n_warp + (lane & 3) * 2;
    if (proj < 2) {
#pragma unroll
        for (int im = 0; im < MT; im++)
#pragma unroll
            for (int jn = 0; jn < NT; jn++) {
                const float* d = acc[im][jn];
                int r0 = rbase + im * 16;
                int c  = cbase + jn * 8;
                uint32_t h, l;
                split2(d[0], d[1], h, l);
                long b0a = (long)r0 * ldc + c;
                *reinterpret_cast<uint32_t*>(C_h + b0a) = h;
                *reinterpret_cast<uint32_t*>(C_l + b0a) = l;
                split2(d[2], d[3], h, l);
                long b1a = (long)(r0 + 8) * ldc + c;
                *reinterpret_cast<uint32_t*>(C_h + b1a) = h;
                *reinterpret_cast<uint32_t*>(C_l + b1a) = l;
            }
    } else {
#pragma unroll
        for (int im = 0; im < MT; im++)
#pragma unroll
            for (int jn = 0; jn < NT; jn++) {
                const float* d = acc[im][jn];
                int r0 = rbase + im * 16;
                int c  = cbase + jn * 8;
#pragma unroll
                for (int e = 0; e < 4; e++) {
                    int m = r0 + (e >> 1) * 8;
                    int n = c + (e & 1);
                    float f = d[e];
                    __half hv = __float2half_rn(f);
                    __half lv = __float2half_rn(f - __half2float(hv));
                    int b2 = m >> 11, s2 = m & (S_ - 1);
                    int hidx = n >> 6, hd = n & 63;
                    long addr = (((long)b2 * H_ + hidx) * HD_ + hd) * S_ + s2;
                    *reinterpret_cast<unsigned short*>(C_h + addr) = __half_as_ushort(hv);
                    *reinterpret_cast<unsigned short*>(C_l + addr) = __half_as_ushort(lv);
                }
            }
    }
}

// ---------------------------------------------------------------------------
// Generic batched GEMM, fp32 epilogue (*alpha). AP=1: A hi-only single pass.
// Used for scores (A=q) and final (A=cat).
// ---------------------------------------------------------------------------
template <int AP>
__global__ __launch_bounds__(256, 2) void mma_gemm_f32(
    const __nv_bfloat16* __restrict__ Ah, const __nv_bfloat16* __restrict__ Al,
    const __nv_bfloat16* __restrict__ Bh,
    float* __restrict__ C,
    int K, int lda, int ldb, int ldc,
    long offAb, long offAh_, long offBb, long offBh_, long offCb, long offCh_,
    int Hdiv, float alpha)
{
    GEMM_PREAMBLE(AP)
    const int z = blockIdx.z;
    const int bb = z / Hdiv, hh = z % Hdiv;
    const __nv_bfloat16* A_h = Ah + (long)bb * offAb + (long)hh * offAh_;
    const __nv_bfloat16* A_l = Al ? (Al + (long)bb * offAb + (long)hh * offAh_) : nullptr;
    const __nv_bfloat16* B_h = Bh + (long)bb * offBb + (long)hh * offBh_;
    const long coff = (long)bb * offCb + (long)hh * offCh_;
    const int m0 = blockIdx.y * BM;
    const int n0 = blockIdx.x * BN;

    GEMM_MAINLOOP(A_h, A_l, B_h);

    const int rbase = m0 + m_warp + (lane >> 2);
    const int cbase = n0 + n_warp + (lane & 3) * 2;
#pragma unroll
    for (int im = 0; im < MT; im++)
#pragma unroll
        for (int jn = 0; jn < NT; jn++) {
            const float* d = acc[im][jn];
            int r0 = rbase + im * 16;
            int c  = cbase + jn * 8;
            *reinterpret_cast<float2*>(C + coff + (long)r0 * ldc + c) =
                make_float2(d[0] * alpha, d[1] * alpha);
            *reinterpret_cast<float2*>(C + coff + (long)(r0 + 8) * ldc + c) =
                make_float2(d[2] * alpha, d[3] * alpha);
        }
}

// ---------------------------------------------------------------------------
// AV GEMM: A = softmax weights fp32 -> fp16 hi only; B = v^T fp16-hi.
// BM=128, BN=64, BK=32, single-pass MMA.
// ---------------------------------------------------------------------------
__global__ __launch_bounds__(256, 2) void mma_gemm_av(
    const float* __restrict__ Afp,
    const __nv_bfloat16* __restrict__ Bh,
    __nv_bfloat16* __restrict__ Chi, __nv_bfloat16* __restrict__ Clo,
    int K, int lda, int ldb, int ldc,
    long offAb, long offAh_, long offBb, long offBh_, long offCb, long offCh_,
    int Hdiv)
{
    constexpr int BM = 128, BN = 64, BK = 32;
    constexpr int ROWB = 80;
    constexpr int ATILE = BM * ROWB;
    constexpr int BTILE = BN * ROWB;
    constexpr int STAGE = ATILE + BTILE;
    constexpr int AF4 = 2, BF4 = 1;
    constexpr int WARPS_M = 4, WARPS_N = 2;
    constexpr int MT = 2, NT = 4;

    extern __shared__ char smem[];
    const uint32_t sbase = smem_u32(smem);

    const int tid  = threadIdx.x;
    const int lane = tid & 31;
    const int wid  = tid >> 5;

    const int z = blockIdx.z;
    const int bb = z / Hdiv, hh = z % Hdiv;
    const float* A = Afp + (long)bb * offAb + (long)hh * offAh_;
    const __nv_bfloat16* B_h = Bh + (long)bb * offBb + (long)hh * offBh_;
    const long coff = (long)bb * offCb + (long)hh * offCh_;

    const int m0 = blockIdx.y * BM;
    const int n0 = blockIdx.x * BN;

    const int m_warp = (wid % WARPS_M) * (BM / WARPS_M);
    const int n_warp = (wid / WARPS_M) * (BN / WARPS_N);

    const uint32_t OFF_AH = 0, OFF_BH = ATILE;

    float acc[MT][NT][4];
#pragma unroll
    for (int i = 0; i < MT; i++)
#pragma unroll
        for (int j = 0; j < NT; j++)
#pragma unroll
            for (int r = 0; r < 4; r++) acc[i][j][r] = 0.0f;

    uint4 rAh[AF4], rBh[BF4];

    auto gload = [&](int it) {
        const int kt = it * BK;
#pragma unroll
        for (int i = 0; i < AF4; i++) {
            int f4 = tid + i * 256;
            int row = f4 >> 2, c8 = f4 & 3;
            long g = (long)(m0 + row) * lda + kt + c8 * 8;
            float4 x0 = *reinterpret_cast<const float4*>(A + g);
            float4 x1 = *reinterpret_cast<const float4*>(A + g + 4);
            rAh[i] = make_uint4(pack_h2(x0.x, x0.y), pack_h2(x0.z, x0.w),
                                pack_h2(x1.x, x1.y), pack_h2(x1.z, x1.w));
        }
#pragma unroll
        for (int i = 0; i < BF4; i++) {
            int f4 = tid + i * 256;
            int row = f4 >> 2, c8 = f4 & 3;
            long g = (long)(n0 + row) * ldb + kt + c8 * 8;
            rBh[i] = *reinterpret_cast<const uint4*>(B_h + g);
        }
    };

    auto sstore = [&](int buf) {
        char* st = smem + buf * STAGE;
#pragma unroll
        for (int i = 0; i < AF4; i++) {
            int f4 = tid + i * 256;
            int row = f4 >> 2, c8 = f4 & 3;
            uint32_t o = row * ROWB + c8 * 16;
            *reinterpret_cast<uint4*>(st + OFF_AH + o) = rAh[i];
        }
#pragma unroll
        for (int i = 0; i < BF4; i++) {
            int f4 = tid + i * 256;
            int row = f4 >> 2, c8 = f4 & 3;
            uint32_t o = row * ROWB + c8 * 16;
            *reinterpret_cast<uint4*>(st + OFF_BH + o) = rBh[i];
        }
    };

    auto compute = [&](int buf) {
        const uint32_t st = sbase + buf * STAGE;
        const uint32_t a_row = m_warp + (lane & 15);
        const uint32_t a_k8  = (lane >> 4) * 16;
        const uint32_t b_row = n_warp + (lane & 7) + ((lane >> 4) & 1) * 8;
        const uint32_t b_k8  = ((lane >> 3) & 1) * 16;
#pragma unroll
        for (int ks = 0; ks < 2; ks++) {
            const uint32_t kbyte = ks * 32;
            uint32_t ah[MT][4];
#pragma unroll
            for (int im = 0; im < MT; im++) {
                uint32_t addr = st + OFF_AH + (a_row + im * 16) * ROWB + kbyte + a_k8;
                ldmat_x4(ah[im][0], ah[im][1], ah[im][2], ah[im][3], addr);
            }
            uint32_t bh[NT][2];
#pragma unroll
            for (int j2 = 0; j2 < NT / 2; j2++) {
                uint32_t addr = st + OFF_BH + (b_row + j2 * 16) * ROWB + kbyte + b_k8;
                ldmat_x4(bh[j2*2][0], bh[j2*2][1], bh[j2*2+1][0], bh[j2*2+1][1], addr);
            }
#pragma unroll
            for (int im = 0; im < MT; im++)
#pragma unroll
                for (int jn = 0; jn < NT; jn++) {
                    float* d = acc[im][jn];
                    mma_f16(d[0], d[1], d[2], d[3],
                            ah[im][0], ah[im][1], ah[im][2], ah[im][3],
                            bh[jn][0], bh[jn][1]);
                }
        }
    };

    const int NI = K / BK;
    gload(0);
    sstore(0);
    __syncthreads();
    int buf = 0;
    for (int it = 1; it < NI; it++) {
        gload(it);
        compute(buf);
        sstore(buf ^ 1);
        __syncthreads();
        buf ^= 1;
    }
    compute(buf);

    const int rbase = m0 + m_warp + (lane >> 2);
    const int cbase = n0 + n_warp + (lane & 3) * 2;
#pragma unroll
    for (int im = 0; im < MT; im++) {
#pragma unroll
        for (int jn = 0; jn < NT; jn++) {
            const float* d = acc[im][jn];
            int r0 = rbase + im * 16;
            int c  = cbase + jn * 8;
            uint32_t h, l;
            split2(d[0], d[1], h, l);
            long b0a = coff + (long)r0 * ldc + c;
            *reinterpret_cast<uint32_t*>(Chi + b0a) = h;
            *reinterpret_cast<uint32_t*>(Clo + b0a) = l;
            split2(d[2], d[3], h, l);
            long b1a = coff + (long)(r0 + 8) * ldc + c;
            *reinterpret_cast<uint32_t*>(Chi + b1a) = h;
            *reinterpret_cast<uint32_t*>(Clo + b1a) = l;
        }
    }
}

// ---------------------------------------------------------------------------
// Register-resident softmax: one read + one write per element.
// ---------------------------------------------------------------------------
__global__ __launch_bounds__(256) void softmax_rows2048(float* __restrict__ W)
{
    float4* p = reinterpret_cast<float4*>(W + (long)blockIdx.x * S_);
    const int t = threadIdx.x;
    const int lane = t & 31, warp = t >> 5;

    __shared__ float red[8];

    float4 x0 = p[t];
    float4 x1 = p[t + 256];

    float m = fmaxf(fmaxf(fmaxf(x0.x, x0.y), fmaxf(x0.z, x0.w)),
                    fmaxf(fmaxf(x1.x, x1.y), fmaxf(x1.z, x1.w)));
#pragma unroll
    for (int s = 16; s > 0; s >>= 1)
        m = fmaxf(m, __shfl_xor_sync(0xFFFFFFFFu, m, s));
    if (lane == 0) red[warp] = m;
    __syncthreads();
    {
        float v = red[lane & 7];
#pragma unroll
        for (int s = 4; s > 0; s >>= 1)
            v = fmaxf(v, __shfl_xor_sync(0xFFFFFFFFu, v, s));
        m = v;
    }

    x0.x = __expf(x0.x - m); x0.y = __expf(x0.y - m);
    x0.z = __expf(x0.z - m); x0.w = __expf(x0.w - m);
    x1.x = __expf(x1.x - m); x1.y = __expf(x1.y - m);
    x1.z = __expf(x1.z - m); x1.w = __expf(x1.w - m);
    float sum = (x0.x + x0.y) + (x0.z + x0.w) + (x1.x + x1.y) + (x1.z + x1.w);
#pragma unroll
    for (int s = 16; s > 0; s >>= 1)
        sum += __shfl_xor_sync(0xFFFFFFFFu, sum, s);
    __syncthreads();
    if (lane == 0) red[warp] = sum;
    __syncthreads();
    {
        float v = red[lane & 7];
#pragma unroll
        for (int s = 4; s > 0; s >>= 1)
            v += __shfl_xor_sync(0xFFFFFFFFu, v, s);
        sum = v;
    }

    const float inv = 1.0f / sum;
    x0.x *= inv; x0.y *= inv; x0.z *= inv; x0.w *= inv;
    x1.x *= inv; x1.y *= inv; x1.z *= inv; x1.w *= inv;
    p[t] = x0;
    p[t + 256] = x1;
}

// ---------------------------------------------------------------------------
extern "C" void kernel_launch(void* const* d_in, const int* in_sizes, int n_in,
                              void* d_out, int out_size)
{
    const float* Q  = (const float*)d_in[0];
    const float* K  = (const float*)d_in[1];
    const float* V  = (const float*)d_in[2];
    const float* Wq = (const float*)d_in[3];
    const float* Wk = (const float*)d_in[4];
    const float* Wv = (const float*)d_in[5];
    const float* Wo = (const float*)d_in[6];

    float* out = (float*)d_out;
    float* final_out = out;                       // [B,S,D]
    float* weights   = out + (long)B_ * S_ * D_;  // [B,H,S,S]

    __nv_bfloat16 *iQh,*iQl,*iKh,*iKl,*iVh,*iVl;
    __nv_bfloat16 *wqh,*wql,*wkh,*wkl,*wvh,*wvl,*woh,*wol;
    __nv_bfloat16 *qh,*ql,*kh,*kl,*vth,*vtl,*cath,*catl;
    cudaGetSymbolAddress((void**)&iQh, g_iQh); cudaGetSymbolAddress((void**)&iQl, g_iQl);
    cudaGetSymbolAddress((void**)&iKh, g_iKh); cudaGetSymbolAddress((void**)&iKl, g_iKl);
    cudaGetSymbolAddress((void**)&iVh, g_iVh); cudaGetSymbolAddress((void**)&iVl, g_iVl);
    cudaGetSymbolAddress((void**)&wqh, g_wqh); cudaGetSymbolAddress((void**)&wql, g_wql);
    cudaGetSymbolAddress((void**)&wkh, g_wkh); cudaGetSymbolAddress((void**)&wkl, g_wkl);
    cudaGetSymbolAddress((void**)&wvh, g_wvh); cudaGetSymbolAddress((void**)&wvl, g_wvl);
    cudaGetSymbolAddress((void**)&woh, g_woh); cudaGetSymbolAddress((void**)&wol, g_wol);
    cudaGetSymbolAddress((void**)&qh,  g_qh);  cudaGetSymbolAddress((void**)&ql,  g_ql);
    cudaGetSymbolAddress((void**)&kh,  g_kh);  cudaGetSymbolAddress((void**)&kl,  g_kl);
    cudaGetSymbolAddress((void**)&vth, g_vth); cudaGetSymbolAddress((void**)&vtl, g_vtl);
    cudaGetSymbolAddress((void**)&cath,g_cath);cudaGetSymbolAddress((void**)&catl,g_catl);

    constexpr int ROWB = 80;
    constexpr int SM_G2 = 2 * (2 * 128 * ROWB + 128 * ROWB);  // 61440 (AP=2)
    constexpr int SM_G1 = 2 * (128 * ROWB + 128 * ROWB);      // 40960 (AP=1)
    constexpr int SM_AV = 2 * (128 * ROWB + 64 * ROWB);       // 30720

    cudaFuncSetAttribute(mma_gemm_qkv,    cudaFuncAttributeMaxDynamicSharedMemorySize, SM_G2);
    cudaFuncSetAttribute(mma_gemm_f32<1>, cudaFuncAttributeMaxDynamicSharedMemorySize, SM_G1);
    cudaFuncSetAttribute(mma_gemm_av,     cudaFuncAttributeMaxDynamicSharedMemorySize, SM_AV);

    // 0) split all fp32 inputs into fp16 hi/lo (single launch)
    {
        dim3 g(BS_*D_/1024, 7, 1);
        split_all<<<g, 256>>>(Q, K, V, Wq, Wk, Wv, Wo,
                              iQh, iKh, iVh, wqh, wkh, wvh, woh,
                              iQl, iKl, iVl, wql, wkl, wvl, wol);
    }

    // 1) merged projections (A 2-pass, B = weight hi only)
    {
        dim3 g(D_/128, BS_/128, 3);
        mma_gemm_qkv<<<g, 256, SM_G2>>>(iQh, iQl, iKh, iKl, iVh, iVl,
                                        wqh, wkh, wvh,
                                        qh, ql, kh, kl, vth, vtl);
    }

    // 2) scores = 0.125 * q @ k^T (A=q hi only, single pass)
    {
        dim3 g(S_/128, S_/128, B_*H_);
        mma_gemm_f32<1><<<g, 256, SM_G1>>>(qh, nullptr, kh, weights,
            HD_, D_, D_, S_,
            (long)S_*D_, (long)HD_, (long)S_*D_, (long)HD_,
            (long)H_*S_*S_, (long)S_*S_, H_, 0.125f);
    }

    // 3) softmax in place
    softmax_rows2048<<<B_*H_*S_, 256>>>(weights);

    // 4) cat = softmax(scores) @ v  (A single-pass fp16)
    {
        dim3 g(1, S_/128, B_*H_);
        mma_gemm_av<<<g, 256, SM_AV>>>(weights, vth,
            cath, catl,
            S_, S_, S_, D_,
            (long)H_*S_*S_, (long)S_*S_,
            (long)H_*HD_*S_, (long)HD_*S_,
            (long)S_*D_, (long)HD_, H_);
    }

    // 5) final = cat @ Wo^T (A=cat hi only, single pass)
    {
        dim3 g(D_/128, BS_/128, 1);
        mma_gemm_f32<1><<<g, 256, SM_G1>>>(cath, nullptr, woh, final_out,
            D_, D_, D_, D_, 0,0,0,0,0,0, 1, 1.0f);
    }
}

// round 17
// speedup vs baseline: 1.5202x; 1.1492x over previous
#include <cuda_runtime.h>
#include <cuda_bf16.h>
#include <cuda_fp16.h>
#include <stdint.h>
#include <math.h>

#define B_ 2
#define S_ 2048
#define D_ 1024
#define H_ 16
#define HD_ 64
#define BS_ (B_*S_)

// ---------------- fp16 scratch (raw 16-bit storage) ----------------
__device__ __nv_bfloat16 g_iQ[BS_*D_], g_iK[BS_*D_], g_iV[BS_*D_];
__device__ __nv_bfloat16 g_wq[D_*D_], g_wk[D_*D_], g_wv[D_*D_], g_wo[D_*D_];
__device__ __nv_bfloat16 g_q[BS_*D_], g_k[BS_*D_];
__device__ __nv_bfloat16 g_vt[BS_*D_];    // [B,H,HD,S]
__device__ __nv_bfloat16 g_cat[BS_*D_];   // [B,S,D]

// ---------------- helpers ----------------
__device__ __forceinline__ uint32_t smem_u32(const void* p){
    uint32_t a;
    asm("{ .reg .u64 t; cvta.to.shared.u64 t, %1; cvt.u32.u64 %0, t; }" : "=r"(a) : "l"(p));
    return a;
}
__device__ __forceinline__ void cp_async16(uint32_t saddr, const void* g){
    asm volatile("cp.async.cg.shared.global [%0], [%1], 16;" :: "r"(saddr), "l"(g));
}
#define CP_COMMIT() asm volatile("cp.async.commit_group;" ::: "memory")
#define CP_WAIT1()  asm volatile("cp.async.wait_group 1;"  ::: "memory")

__device__ __forceinline__ void ldmat_x4(uint32_t& r0, uint32_t& r1, uint32_t& r2,
                                         uint32_t& r3, uint32_t addr){
    asm volatile("ldmatrix.sync.aligned.m8n8.x4.shared.b16 {%0,%1,%2,%3}, [%4];"
        : "=r"(r0), "=r"(r1), "=r"(r2), "=r"(r3) : "r"(addr));
}
// fp16 MMA, fp32 accumulate
__device__ __forceinline__ void mma_f16(float& d0, float& d1, float& d2, float& d3,
                                        uint32_t a0, uint32_t a1, uint32_t a2, uint32_t a3,
                                        uint32_t b0, uint32_t b1){
    asm volatile("mma.sync.aligned.m16n8k16.row.col.f32.f16.f16.f32 "
        "{%0,%1,%2,%3}, {%4,%5,%6,%7}, {%8,%9}, {%0,%1,%2,%3};"
        : "+f"(d0), "+f"(d1), "+f"(d2), "+f"(d3)
        : "r"(a0), "r"(a1), "r"(a2), "r"(a3), "r"(b0), "r"(b1));
}
// pack two floats as fp16x2
__device__ __forceinline__ uint32_t pack_h2(float a, float b){
    __half ha = __float2half_rn(a), hb = __float2half_rn(b);
    return ((uint32_t)__half_as_ushort(ha)) | (((uint32_t)__half_as_ushort(hb)) << 16);
}

// ---------------- one-shot fp32 -> fp16 conversion of all 7 tensors --------
__global__ __launch_bounds__(256) void cvt_all(
    const float* __restrict__ i0, const float* __restrict__ i1,
    const float* __restrict__ i2, const float* __restrict__ i3,
    const float* __restrict__ i4, const float* __restrict__ i5,
    const float* __restrict__ i6,
    __nv_bfloat16* __restrict__ o0, __nv_bfloat16* __restrict__ o1,
    __nv_bfloat16* __restrict__ o2, __nv_bfloat16* __restrict__ o3,
    __nv_bfloat16* __restrict__ o4, __nv_bfloat16* __restrict__ o5,
    __nv_bfloat16* __restrict__ o6)
{
    const int t = blockIdx.y;
    const int n = (t < 3) ? BS_*D_ : D_*D_;
    int i = (blockIdx.x * 256 + threadIdx.x) * 4;
    if (i >= n) return;
    const float* in = (t==0)?i0:(t==1)?i1:(t==2)?i2:(t==3)?i3:(t==4)?i4:(t==5)?i5:i6;
    __nv_bfloat16* o = (t==0)?o0:(t==1)?o1:(t==2)?o2:(t==3)?o3:(t==4)?o4:(t==5)?o5:o6;
    float4 x = *reinterpret_cast<const float4*>(in + i);
    *reinterpret_cast<uint2*>(o + i) =
        make_uint2(pack_h2(x.x, x.y), pack_h2(x.z, x.w));
}

// ===========================================================================
// Shared GEMM machinery: BM=128, BN=128, BK=32, 8 warps, 2-stage cp.async,
// occupancy 2, 80B padded rows. Plain fp16 operands, fp32 accumulate.
// ===========================================================================
#define GEMM_CONSTS \
    constexpr int BM = 128, BN = 128, BK = 32; \
    constexpr int ROWB = 80; \
    constexpr int ATILE = BM * ROWB; \
    constexpr int BTILE = BN * ROWB; \
    constexpr int STAGE = ATILE + BTILE; \
    constexpr int WARPS_M = 2, WARPS_N = 4; \
    constexpr int MT = 4, NT = 4; \
    (void)sizeof(char[WARPS_M + WARPS_N]);

#define GEMM_ISSUE(st, A_p, B_p, kt) do { \
    _Pragma("unroll") \
    for (int i_ = 0; i_ < 2; i_++) { \
        int row_ = l_row + i_ * 64; \
        long g_ = (long)(m0 + row_) * lda + (kt) + l_c8 * 8; \
        uint32_t o_ = so + i_ * 64 * ROWB; \
        cp_async16((st) + o_, (A_p) + g_); \
    } \
    _Pragma("unroll") \
    for (int i_ = 0; i_ < 2; i_++) { \
        int row_ = l_row + i_ * 64; \
        long g_ = (long)(n0 + row_) * ldb + (kt) + l_c8 * 8; \
        uint32_t o_ = so + i_ * 64 * ROWB; \
        cp_async16((st) + ATILE + o_, (B_p) + g_); \
    } \
} while(0)

#define GEMM_COMPUTE(st) do { \
    const uint32_t a_row_ = m_warp + (lane & 15); \
    const uint32_t a_k8_  = (lane >> 4) * 16; \
    const uint32_t b_row_ = n_warp + (lane & 7) + ((lane >> 4) & 1) * 8; \
    const uint32_t b_k8_  = ((lane >> 3) & 1) * 16; \
    _Pragma("unroll") \
    for (int ks_ = 0; ks_ < 2; ks_++) { \
        const uint32_t kb_ = ks_ * 32; \
        uint32_t ah_[MT][4]; \
        _Pragma("unroll") \
        for (int im_ = 0; im_ < MT; im_++) { \
            uint32_t ad_ = (st) + (a_row_ + im_ * 16) * ROWB + kb_ + a_k8_; \
            ldmat_x4(ah_[im_][0], ah_[im_][1], ah_[im_][2], ah_[im_][3], ad_); \
        } \
        uint32_t bh_[NT][2]; \
        _Pragma("unroll") \
        for (int j2_ = 0; j2_ < NT/2; j2_++) { \
            uint32_t ad_ = (st) + ATILE + (b_row_ + j2_ * 16) * ROWB + kb_ + b_k8_; \
            ldmat_x4(bh_[j2_*2][0], bh_[j2_*2][1], bh_[j2_*2+1][0], bh_[j2_*2+1][1], ad_); \
        } \
        _Pragma("unroll") \
        for (int im_ = 0; im_ < MT; im_++) \
        _Pragma("unroll") \
        for (int jn_ = 0; jn_ < NT; jn_++) { \
            float* d_ = acc[im_][jn_]; \
            mma_f16(d_[0], d_[1], d_[2], d_[3], \
                    ah_[im_][0], ah_[im_][1], ah_[im_][2], ah_[im_][3], \
                    bh_[jn_][0], bh_[jn_][1]); \
        } \
    } \
} while(0)

#define GEMM_MAINLOOP(A_p, B_p) do { \
    const int NI_ = K / BK; \
    GEMM_ISSUE(sbase, A_p, B_p, 0); \
    CP_COMMIT(); \
    if (NI_ > 1) GEMM_ISSUE(sbase + STAGE, A_p, B_p, BK); \
    CP_COMMIT(); \
    for (int it_ = 0; it_ < NI_; it_++) { \
        CP_WAIT1(); \
        __syncthreads(); \
        GEMM_COMPUTE(sbase + (it_ & 1) * STAGE); \
        __syncthreads(); \
        if (it_ + 2 < NI_) \
            GEMM_ISSUE(sbase + (it_ & 1) * STAGE, A_p, B_p, (it_ + 2) * BK); \
        CP_COMMIT(); \
    } \
} while(0)

#define GEMM_PREAMBLE \
    GEMM_CONSTS \
    extern __shared__ char smem[]; \
    const uint32_t sbase = smem_u32(smem); \
    const int tid  = threadIdx.x; \
    const int lane = tid & 31; \
    const int wid  = tid >> 5; \
    const int m_warp = (wid % WARPS_M) * (BM / WARPS_M); \
    const int n_warp = (wid / WARPS_M) * (BN / WARPS_N); \
    const int l_row = tid >> 2; \
    const int l_c8  = tid & 3; \
    const uint32_t so = l_row * ROWB + l_c8 * 16; \
    float acc[MT][NT][4]; \
    _Pragma("unroll") \
    for (int i_ = 0; i_ < MT; i_++) \
    _Pragma("unroll") \
    for (int j_ = 0; j_ < NT; j_++) \
    _Pragma("unroll") \
    for (int r_ = 0; r_ < 4; r_++) acc[i_][j_][r_] = 0.0f;

// ---------------------------------------------------------------------------
// Merged Q/K/V projection GEMM. proj 0,1: fp16 store. proj 2: transposed fp16.
// ---------------------------------------------------------------------------
__global__ __launch_bounds__(256, 2) void mma_gemm_qkv(
    const __nv_bfloat16* __restrict__ iQ, const __nv_bfloat16* __restrict__ iK,
    const __nv_bfloat16* __restrict__ iV,
    const __nv_bfloat16* __restrict__ wq, const __nv_bfloat16* __restrict__ wk,
    const __nv_bfloat16* __restrict__ wv,
    __nv_bfloat16* __restrict__ q, __nv_bfloat16* __restrict__ k,
    __nv_bfloat16* __restrict__ vt)
{
    GEMM_PREAMBLE
    const int K = D_, lda = D_, ldb = D_, ldc = D_;
    const int m0 = blockIdx.y * BM;
    const int n0 = blockIdx.x * BN;
    const int proj = blockIdx.z;

    const __nv_bfloat16* A = (proj==0) ? iQ : (proj==1) ? iK : iV;
    const __nv_bfloat16* Bm = (proj==0) ? wq : (proj==1) ? wk : wv;
    __nv_bfloat16* C = (proj==0) ? q : (proj==1) ? k : vt;

    GEMM_MAINLOOP(A, Bm);

    const int rbase = m0 + m_warp + (lane >> 2);
    const int cbase = n0 + n_warp + (lane & 3) * 2;
    if (proj < 2) {
#pragma unroll
        for (int im = 0; im < MT; im++)
#pragma unroll
            for (int jn = 0; jn < NT; jn++) {
                const float* d = acc[im][jn];
                int r0 = rbase + im * 16;
                int c  = cbase + jn * 8;
                *reinterpret_cast<uint32_t*>(C + (long)r0 * ldc + c) = pack_h2(d[0], d[1]);
                *reinterpret_cast<uint32_t*>(C + (long)(r0 + 8) * ldc + c) = pack_h2(d[2], d[3]);
            }
    } else {
#pragma unroll
        for (int im = 0; im < MT; im++)
#pragma unroll
            for (int jn = 0; jn < NT; jn++) {
                const float* d = acc[im][jn];
                int r0 = rbase + im * 16;
                int c  = cbase + jn * 8;
#pragma unroll
                for (int e = 0; e < 4; e++) {
                    int m = r0 + (e >> 1) * 8;
                    int n = c + (e & 1);
                    __half hv = __float2half_rn(d[e]);
                    int b2 = m >> 11, s2 = m & (S_ - 1);
                    int hidx = n >> 6, hd = n & 63;
                    long addr = (((long)b2 * H_ + hidx) * HD_ + hd) * S_ + s2;
                    *reinterpret_cast<unsigned short*>(C + addr) = __half_as_ushort(hv);
                }
            }
    }
}

// ---------------------------------------------------------------------------
// Generic batched GEMM, fp32 epilogue (*alpha). Scores + final GEMM.
// ---------------------------------------------------------------------------
__global__ __launch_bounds__(256, 2) void mma_gemm_f32(
    const __nv_bfloat16* __restrict__ Am, const __nv_bfloat16* __restrict__ Bm,
    float* __restrict__ C,
    int K, int lda, int ldb, int ldc,
    long offAb, long offAh_, long offBb, long offBh_, long offCb, long offCh_,
    int Hdiv, float alpha)
{
    GEMM_PREAMBLE
    const int z = blockIdx.z;
    const int bb = z / Hdiv, hh = z % Hdiv;
    const __nv_bfloat16* A = Am + (long)bb * offAb + (long)hh * offAh_;
    const __nv_bfloat16* Bp = Bm + (long)bb * offBb + (long)hh * offBh_;
    const long coff = (long)bb * offCb + (long)hh * offCh_;
    const int m0 = blockIdx.y * BM;
    const int n0 = blockIdx.x * BN;

    GEMM_MAINLOOP(A, Bp);

    const int rbase = m0 + m_warp + (lane >> 2);
    const int cbase = n0 + n_warp + (lane & 3) * 2;
#pragma unroll
    for (int im = 0; im < MT; im++)
#pragma unroll
        for (int jn = 0; jn < NT; jn++) {
            const float* d = acc[im][jn];
            int r0 = rbase + im * 16;
            int c  = cbase + jn * 8;
            *reinterpret_cast<float2*>(C + coff + (long)r0 * ldc + c) =
                make_float2(d[0] * alpha, d[1] * alpha);
            *reinterpret_cast<float2*>(C + coff + (long)(r0 + 8) * ldc + c) =
                make_float2(d[2] * alpha, d[3] * alpha);
        }
}

// ---------------------------------------------------------------------------
// AV GEMM: A = softmax weights fp32 -> fp16 on load; B = v^T fp16.
// BM=128, BN=64, BK=32. fp16 store (cat).
// ---------------------------------------------------------------------------
__global__ __launch_bounds__(256, 2) void mma_gemm_av(
    const float* __restrict__ Afp,
    const __nv_bfloat16* __restrict__ Bm,
    __nv_bfloat16* __restrict__ C,
    int K, int lda, int ldb, int ldc,
    long offAb, long offAh_, long offBb, long offBh_, long offCb, long offCh_,
    int Hdiv)
{
    constexpr int BM = 128, BN = 64, BK = 32;
    constexpr int ROWB = 80;
    constexpr int ATILE = BM * ROWB;
    constexpr int BTILE = BN * ROWB;
    constexpr int STAGE = ATILE + BTILE;
    constexpr int AF4 = 2, BF4 = 1;
    constexpr int WARPS_M = 4, WARPS_N = 2;
    constexpr int MT = 2, NT = 4;

    extern __shared__ char smem[];
    const uint32_t sbase = smem_u32(smem);

    const int tid  = threadIdx.x;
    const int lane = tid & 31;
    const int wid  = tid >> 5;

    const int z = blockIdx.z;
    const int bb = z / Hdiv, hh = z % Hdiv;
    const float* A = Afp + (long)bb * offAb + (long)hh * offAh_;
    const __nv_bfloat16* Bp = Bm + (long)bb * offBb + (long)hh * offBh_;
    const long coff = (long)bb * offCb + (long)hh * offCh_;

    const int m0 = blockIdx.y * BM;
    const int n0 = blockIdx.x * BN;

    const int m_warp = (wid % WARPS_M) * (BM / WARPS_M);
    const int n_warp = (wid / WARPS_M) * (BN / WARPS_N);

    const uint32_t OFF_A = 0, OFF_B = ATILE;

    float acc[MT][NT][4];
#pragma unroll
    for (int i = 0; i < MT; i++)
#pragma unroll
        for (int j = 0; j < NT; j++)
#pragma unroll
            for (int r = 0; r < 4; r++) acc[i][j][r] = 0.0f;

    uint4 rA[AF4], rB[BF4];

    auto gload = [&](int it) {
        const int kt = it * BK;
#pragma unroll
        for (int i = 0; i < AF4; i++) {
            int f4 = tid + i * 256;
            int row = f4 >> 2, c8 = f4 & 3;
            long g = (long)(m0 + row) * lda + kt + c8 * 8;
            float4 x0 = *reinterpret_cast<const float4*>(A + g);
            float4 x1 = *reinterpret_cast<const float4*>(A + g + 4);
            rA[i] = make_uint4(pack_h2(x0.x, x0.y), pack_h2(x0.z, x0.w),
                               pack_h2(x1.x, x1.y), pack_h2(x1.z, x1.w));
        }
#pragma unroll
        for (int i = 0; i < BF4; i++) {
            int f4 = tid + i * 256;
            int row = f4 >> 2, c8 = f4 & 3;
            long g = (long)(n0 + row) * ldb + kt + c8 * 8;
            rB[i] = *reinterpret_cast<const uint4*>(Bp + g);
        }
    };

    auto sstore = [&](int buf) {
        char* st = smem + buf * STAGE;
#pragma unroll
        for (int i = 0; i < AF4; i++) {
            int f4 = tid + i * 256;
            int row = f4 >> 2, c8 = f4 & 3;
            *reinterpret_cast<uint4*>(st + OFF_A + row * ROWB + c8 * 16) = rA[i];
        }
#pragma unroll
        for (int i = 0; i < BF4; i++) {
            int f4 = tid + i * 256;
            int row = f4 >> 2, c8 = f4 & 3;
            *reinterpret_cast<uint4*>(st + OFF_B + row * ROWB + c8 * 16) = rB[i];
        }
    };

    auto compute = [&](int buf) {
        const uint32_t st = sbase + buf * STAGE;
        const uint32_t a_row = m_warp + (lane & 15);
        const uint32_t a_k8  = (lane >> 4) * 16;
        const uint32_t b_row = n_warp + (lane & 7) + ((lane >> 4) & 1) * 8;
        const uint32_t b_k8  = ((lane >> 3) & 1) * 16;
#pragma unroll
        for (int ks = 0; ks < 2; ks++) {
            const uint32_t kbyte = ks * 32;
            uint32_t ah[MT][4];
#pragma unroll
            for (int im = 0; im < MT; im++) {
                uint32_t addr = st + OFF_A + (a_row + im * 16) * ROWB + kbyte + a_k8;
                ldmat_x4(ah[im][0], ah[im][1], ah[im][2], ah[im][3], addr);
            }
            uint32_t bh[NT][2];
#pragma unroll
            for (int j2 = 0; j2 < NT / 2; j2++) {
                uint32_t addr = st + OFF_B + (b_row + j2 * 16) * ROWB + kbyte + b_k8;
                ldmat_x4(bh[j2*2][0], bh[j2*2][1], bh[j2*2+1][0], bh[j2*2+1][1], addr);
            }
#pragma unroll
            for (int im = 0; im < MT; im++)
#pragma unroll
                for (int jn = 0; jn < NT; jn++) {
                    float* d = acc[im][jn];
                    mma_f16(d[0], d[1], d[2], d[3],
                            ah[im][0], ah[im][1], ah[im][2], ah[im][3],
                            bh[jn][0], bh[jn][1]);
                }
        }
    };

    const int NI = K / BK;
    gload(0);
    sstore(0);
    __syncthreads();
    int buf = 0;
    for (int it = 1; it < NI; it++) {
        gload(it);
        compute(buf);
        sstore(buf ^ 1);
        __syncthreads();
        buf ^= 1;
    }
    compute(buf);

    const int rbase = m0 + m_warp + (lane >> 2);
    const int cbase = n0 + n_warp + (lane & 3) * 2;
#pragma unroll
    for (int im = 0; im < MT; im++) {
#pragma unroll
        for (int jn = 0; jn < NT; jn++) {
            const float* d = acc[im][jn];
            int r0 = rbase + im * 16;
            int c  = cbase + jn * 8;
            *reinterpret_cast<uint32_t*>(C + coff + (long)r0 * ldc + c) = pack_h2(d[0], d[1]);
            *reinterpret_cast<uint32_t*>(C + coff + (long)(r0 + 8) * ldc + c) = pack_h2(d[2], d[3]);
        }
    }
}

// ---------------------------------------------------------------------------
// Register-resident softmax: one read + one write per element.
// ---------------------------------------------------------------------------
__global__ __launch_bounds__(256) void softmax_rows2048(float* __restrict__ W)
{
    float4* p = reinterpret_cast<float4*>(W + (long)blockIdx.x * S_);
    const int t = threadIdx.x;
    const int lane = t & 31, warp = t >> 5;

    __shared__ float red[8];

    float4 x0 = p[t];
    float4 x1 = p[t + 256];

    float m = fmaxf(fmaxf(fmaxf(x0.x, x0.y), fmaxf(x0.z, x0.w)),
                    fmaxf(fmaxf(x1.x, x1.y), fmaxf(x1.z, x1.w)));
#pragma unroll
    for (int s = 16; s > 0; s >>= 1)
        m = fmaxf(m, __shfl_xor_sync(0xFFFFFFFFu, m, s));
    if (lane == 0) red[warp] = m;
    __syncthreads();
    {
        float v = red[lane & 7];
#pragma unroll
        for (int s = 4; s > 0; s >>= 1)
            v = fmaxf(v, __shfl_xor_sync(0xFFFFFFFFu, v, s));
        m = v;
    }

    x0.x = __expf(x0.x - m); x0.y = __expf(x0.y - m);
    x0.z = __expf(x0.z - m); x0.w = __expf(x0.w - m);
    x1.x = __expf(x1.x - m); x1.y = __expf(x1.y - m);
    x1.z = __expf(x1.z - m); x1.w = __expf(x1.w - m);
    float sum = (x0.x + x0.y) + (x0.z + x0.w) + (x1.x + x1.y) + (x1.z + x1.w);
#pragma unroll
    for (int s = 16; s > 0; s >>= 1)
        sum += __shfl_xor_sync(0xFFFFFFFFu, sum, s);
    __syncthreads();
    if (lane == 0) red[warp] = sum;
    __syncthreads();
    {
        float v = red[lane & 7];
#pragma unroll
        for (int s = 4; s > 0; s >>= 1)
            v += __shfl_xor_sync(0xFFFFFFFFu, v, s);
        sum = v;
    }

    const float inv = 1.0f / sum;
    x0.x *= inv; x0.y *= inv; x0.z *= inv; x0.w *= inv;
    x1.x *= inv; x1.y *= inv; x1.z *= inv; x1.w *= inv;
    p[t] = x0;
    p[t + 256] = x1;
}

// ---------------------------------------------------------------------------
extern "C" void kernel_launch(void* const* d_in, const int* in_sizes, int n_in,
                              void* d_out, int out_size)
{
    const float* Q  = (const float*)d_in[0];
    const float* K  = (const float*)d_in[1];
    const float* V  = (const float*)d_in[2];
    const float* Wq = (const float*)d_in[3];
    const float* Wk = (const float*)d_in[4];
    const float* Wv = (const float*)d_in[5];
    const float* Wo = (const float*)d_in[6];

    float* out = (float*)d_out;
    float* final_out = out;                       // [B,S,D]
    float* weights   = out + (long)B_ * S_ * D_;  // [B,H,S,S]

    __nv_bfloat16 *iQ,*iK,*iV,*wq,*wk,*wv,*wo,*q,*k,*vt,*cat;
    cudaGetSymbolAddress((void**)&iQ, g_iQ);
    cudaGetSymbolAddress((void**)&iK, g_iK);
    cudaGetSymbolAddress((void**)&iV, g_iV);
    cudaGetSymbolAddress((void**)&wq, g_wq);
    cudaGetSymbolAddress((void**)&wk, g_wk);
    cudaGetSymbolAddress((void**)&wv, g_wv);
    cudaGetSymbolAddress((void**)&wo, g_wo);
    cudaGetSymbolAddress((void**)&q,  g_q);
    cudaGetSymbolAddress((void**)&k,  g_k);
    cudaGetSymbolAddress((void**)&vt, g_vt);
    cudaGetSymbolAddress((void**)&cat,g_cat);

    constexpr int ROWB = 80;
    constexpr int SM_G  = 2 * (128 * ROWB + 128 * ROWB);  // 40960
    constexpr int SM_AV = 2 * (128 * ROWB + 64 * ROWB);   // 30720

    cudaFuncSetAttribute(mma_gemm_qkv, cudaFuncAttributeMaxDynamicSharedMemorySize, SM_G);
    cudaFuncSetAttribute(mma_gemm_f32, cudaFuncAttributeMaxDynamicSharedMemorySize, SM_G);
    cudaFuncSetAttribute(mma_gemm_av,  cudaFuncAttributeMaxDynamicSharedMemorySize, SM_AV);

    // 0) convert all fp32 inputs to fp16 (single launch)
    {
        dim3 g(BS_*D_/1024, 7, 1);
        cvt_all<<<g, 256>>>(Q, K, V, Wq, Wk, Wv, Wo,
                            iQ, iK, iV, wq, wk, wv, wo);
    }

    // 1) merged projections: q, k (fp16), v -> per-head transposed fp16
    {
        dim3 g(D_/128, BS_/128, 3);
        mma_gemm_qkv<<<g, 256, SM_G>>>(iQ, iK, iV, wq, wk, wv, q, k, vt);
    }

    // 2) scores = 0.125 * q @ k^T -> weights (fp32, pre-softmax)
    {
        dim3 g(S_/128, S_/128, B_*H_);
        mma_gemm_f32<<<g, 256, SM_G>>>(q, k, weights,
            HD_, D_, D_, S_,
            (long)S_*D_, (long)HD_, (long)S_*D_, (long)HD_,
            (long)H_*S_*S_, (long)S_*S_, H_, 0.125f);
    }

    // 3) softmax in place
    softmax_rows2048<<<B_*H_*S_, 256>>>(weights);

    // 4) cat = softmax(scores) @ v
    {
        dim3 g(1, S_/128, B_*H_);
        mma_gemm_av<<<g, 256, SM_AV>>>(weights, vt, cat,
            S_, S_, S_, D_,
            (long)H_*S_*S_, (long)S_*S_,
            (long)H_*HD_*S_, (long)HD_*S_,
            (long)S_*D_, (long)HD_, H_);
    }

    // 5) final = cat @ Wo^T (fp32 out)
    {
        dim3 g(D_/128, BS_/128, 1);
        mma_gemm_f32<<<g, 256, SM_G>>>(cat, wo, final_out,
            D_, D_, D_, D_, 0,0,0,0,0,0, 1, 1.0f);
    }
}